// round 7
// baseline (speedup 1.0000x reference)
#include <cuda_runtime.h>
#include <math.h>

#define N_NODES 100000
#define E_EDGES 1200000
#define EPS 1e-5f

// -------- scratch (device globals; no allocation allowed) --------
__device__ float g_A[N_NODES * 64];     // act (post bn+elu)
__device__ float g_B[N_NODES * 64];     // agg (aggregated features, pre-GEMM)
__device__ float g_C[N_NODES * 64];     // conv output (pre-BN)
__device__ float g_dinv[N_NODES];
__device__ int   g_deg[N_NODES];        // 1 + in-degree
__device__ int   g_rowptr[N_NODES + 1];
__device__ int   g_cursor[N_NODES];
__device__ int2  g_edge[E_EDGES];       // {src, bits(norm)} sorted by dst
__device__ int   g_partial[512];
__device__ int   g_blockOff[512];
__device__ float g_stats[384];          // 3 slices of 128: [0..63] sum, [64..127] sumsq
__device__ unsigned g_barc;             // grid barrier arrive count
__device__ unsigned g_bars;             // grid barrier sense (monotonic)

// ----------------- device-wide barrier (all blocks resident by construction) -----------------
__device__ __forceinline__ void gridbar(int nb) {
    __syncthreads();
    if (threadIdx.x == 0) {
        unsigned old = *(volatile unsigned*)&g_bars;
        __threadfence();
        unsigned arr = atomicAdd(&g_barc, 1u) + 1u;
        if (arr == (unsigned)nb) {
            g_barc = 0;
            __threadfence();
            atomicAdd(&g_bars, 1u);
        } else {
            while (*(volatile unsigned*)&g_bars == old) { __nanosleep(64); }
        }
        __threadfence();
    }
    __syncthreads();
}

// ----------------- phase helpers -----------------
template <int F>
__device__ void dev_gather(const float* __restrict__ act, float* __restrict__ agg,
                           int n, int gtid, int NT) {
    constexpr int G = F / 4;
    const float4* a4 = reinterpret_cast<const float4*>(act);
    for (int gi = gtid; gi < n * G; gi += NT) {
        int node = gi / G;
        int q = gi & (G - 1);
        float di = g_dinv[node];
        float di2 = di * di;
        float4 hv = a4[(size_t)node * G + q];
        float4 a0, a1, a2, a3;
        a0.x = di2 * hv.x; a0.y = di2 * hv.y; a0.z = di2 * hv.z; a0.w = di2 * hv.w;
        a1 = make_float4(0.f, 0.f, 0.f, 0.f);
        a2 = make_float4(0.f, 0.f, 0.f, 0.f);
        a3 = make_float4(0.f, 0.f, 0.f, 0.f);
        int beg = g_rowptr[node], end = g_rowptr[node + 1];
        int i = beg;
        for (; i + 4 <= end; i += 4) {
            int2 e0 = __ldg(&g_edge[i + 0]);
            int2 e1 = __ldg(&g_edge[i + 1]);
            int2 e2 = __ldg(&g_edge[i + 2]);
            int2 e3 = __ldg(&g_edge[i + 3]);
            float4 s0 = a4[(size_t)e0.x * G + q];
            float4 s1 = a4[(size_t)e1.x * G + q];
            float4 s2 = a4[(size_t)e2.x * G + q];
            float4 s3 = a4[(size_t)e3.x * G + q];
            float n0 = __int_as_float(e0.y), n1 = __int_as_float(e1.y);
            float n2 = __int_as_float(e2.y), n3 = __int_as_float(e3.y);
            a0.x = fmaf(n0, s0.x, a0.x); a0.y = fmaf(n0, s0.y, a0.y);
            a0.z = fmaf(n0, s0.z, a0.z); a0.w = fmaf(n0, s0.w, a0.w);
            a1.x = fmaf(n1, s1.x, a1.x); a1.y = fmaf(n1, s1.y, a1.y);
            a1.z = fmaf(n1, s1.z, a1.z); a1.w = fmaf(n1, s1.w, a1.w);
            a2.x = fmaf(n2, s2.x, a2.x); a2.y = fmaf(n2, s2.y, a2.y);
            a2.z = fmaf(n2, s2.z, a2.z); a2.w = fmaf(n2, s2.w, a2.w);
            a3.x = fmaf(n3, s3.x, a3.x); a3.y = fmaf(n3, s3.y, a3.y);
            a3.z = fmaf(n3, s3.z, a3.z); a3.w = fmaf(n3, s3.w, a3.w);
        }
        for (; i < end; i++) {
            int2 e0 = __ldg(&g_edge[i]);
            float4 s0 = a4[(size_t)e0.x * G + q];
            float n0 = __int_as_float(e0.y);
            a1.x = fmaf(n0, s0.x, a1.x); a1.y = fmaf(n0, s0.y, a1.y);
            a1.z = fmaf(n0, s0.z, a1.z); a1.w = fmaf(n0, s0.w, a1.w);
        }
        float4 acc;
        acc.x = (a0.x + a1.x) + (a2.x + a3.x);
        acc.y = (a0.y + a1.y) + (a2.y + a3.y);
        acc.z = (a0.z + a1.z) + (a2.z + a3.z);
        acc.w = (a0.w + a1.w) + (a2.w + a3.w);
        reinterpret_cast<float4*>(agg)[(size_t)node * G + q] = acc;
    }
}

template <int FIN, int FOUT>
__device__ void dev_gemm_stats(const float* __restrict__ agg, const float* __restrict__ W,
                               const float* __restrict__ b, float* __restrict__ outc,
                               float* __restrict__ stats, int n, int gtid, int NT,
                               float* sW, float* sb, float* sSum, float* sSq) {
    for (int i = threadIdx.x; i < FIN * FOUT; i += blockDim.x) sW[i] = W[i];
    if (threadIdx.x < FOUT) {
        sb[threadIdx.x] = b[threadIdx.x];
        sSum[threadIdx.x] = 0.0f;
        sSq[threadIdx.x] = 0.0f;
    }
    __syncthreads();
    int lane = threadIdx.x & 31;
    int iters = (n + NT - 1) / NT;
    for (int it = 0; it < iters; it++) {
        int node = gtid + it * NT;
        bool active = (node < n);
        float xv[FIN];
#pragma unroll
        for (int k = 0; k < FIN; k++) xv[k] = active ? agg[(size_t)node * FIN + k] : 0.0f;
#pragma unroll 4
        for (int j = 0; j < FOUT; j++) {
            float acc = sb[j];
#pragma unroll
            for (int k = 0; k < FIN; k++) acc = fmaf(xv[k], sW[k * FOUT + j], acc);
            if (active) outc[(size_t)node * FOUT + j] = acc;
            float r = active ? fmaxf(acc, 0.0f) : 0.0f;
            float q = r * r;
#pragma unroll
            for (int off = 16; off > 0; off >>= 1) {
                r += __shfl_xor_sync(0xffffffffu, r, off);
                q += __shfl_xor_sync(0xffffffffu, q, off);
            }
            if (lane == 0) { atomicAdd(&sSum[j], r); atomicAdd(&sSq[j], q); }
        }
    }
    __syncthreads();
    if (threadIdx.x < FOUT) {
        atomicAdd(&stats[threadIdx.x], sSum[threadIdx.x]);
        atomicAdd(&stats[64 + threadIdx.x], sSq[threadIdx.x]);
    }
    __syncthreads();
}

template <int F>
__device__ void dev_bn_elu(const float* __restrict__ c, const float* __restrict__ stats,
                           const float* __restrict__ g, const float* __restrict__ bt,
                           float* __restrict__ act, int n, int gtid, int NT) {
    float inv_n = 1.0f / (float)n;
    for (int idx = gtid; idx < n * F; idx += NT) {
        int col = idx & (F - 1);
        float mean = __ldg(&stats[col]) * inv_n;
        float var = __ldg(&stats[64 + col]) * inv_n - mean * mean;
        float v = fmaxf(c[idx], 0.0f);
        float y = (v - mean) * rsqrtf(var + EPS) * __ldg(&g[col]) + __ldg(&bt[col]);
        act[idx] = (y > 0.0f) ? y : expm1f(y);
    }
}

// ----------------- the megakernel -----------------
__global__ void __launch_bounds__(256)
k_mega(const float* __restrict__ x,
       const int* __restrict__ src, const int* __restrict__ dst,
       const float* __restrict__ W1, const float* __restrict__ b1,
       const float* __restrict__ g1, const float* __restrict__ bt1,
       const float* __restrict__ W2, const float* __restrict__ b2,
       const float* __restrict__ g2, const float* __restrict__ bt2,
       const float* __restrict__ W3, const float* __restrict__ b3,
       int n, int e, int nb) {
    __shared__ float sW[32 * 64];
    __shared__ float sAux[192];         // b | sum | sq (64 each)
    __shared__ int sScan[2][512];

    const int NT = nb * 256;
    const int gtid = blockIdx.x * 256 + threadIdx.x;
    float* pS0 = g_stats;
    float* pS1 = g_stats + 128;
    float* pS2 = g_stats + 256;

    // P1: init deg, zero stats
    for (int i = gtid; i < n; i += NT) g_deg[i] = 1;
    for (int i = gtid; i < 384; i += NT) g_stats[i] = 0.0f;
    gridbar(nb);

    // P2: degree count
    for (int i = gtid; i < e; i += NT) atomicAdd(&g_deg[dst[i]], 1);
    gridbar(nb);

    // P3: dinv + per-chunk edge-degree block sums
    const int chunks = (n + 255) >> 8;
    for (int c = blockIdx.x; c < chunks; c += nb) {
        int node = c * 256 + threadIdx.x;
        int d = (node < n) ? g_deg[node] : 1;
        if (node < n) g_dinv[node] = rsqrtf((float)d);
        sScan[0][threadIdx.x] = d - 1;
        __syncthreads();
        for (int off = 128; off > 0; off >>= 1) {
            if (threadIdx.x < off) sScan[0][threadIdx.x] += sScan[0][threadIdx.x + off];
            __syncthreads();
        }
        if (threadIdx.x == 0) g_partial[c] = sScan[0][0];
        __syncthreads();
    }
    gridbar(nb);

    // P4: block 0 scans chunk partials (exclusive) into g_blockOff
    if (blockIdx.x == 0) {
        int t = threadIdx.x;
#pragma unroll
        for (int h = 0; h < 2; h++) {
            int idx = t + h * 256;
            sScan[0][idx] = (idx < chunks) ? g_partial[idx] : 0;
        }
        __syncthreads();
        int p = 0;
        for (int off = 1; off < 512; off <<= 1) {
#pragma unroll
            for (int h = 0; h < 2; h++) {
                int idx = t + h * 256;
                sScan[p ^ 1][idx] = sScan[p][idx] + ((idx >= off) ? sScan[p][idx - off] : 0);
            }
            p ^= 1;
            __syncthreads();
        }
#pragma unroll
        for (int h = 0; h < 2; h++) {
            int idx = t + h * 256;
            if (idx < chunks) g_blockOff[idx] = sScan[p][idx] - g_partial[idx];
        }
    }
    gridbar(nb);

    // P5: rowptr + cursor per chunk (inclusive scan of 256)
    for (int c = blockIdx.x; c < chunks; c += nb) {
        int t = threadIdx.x;
        int node = c * 256 + t;
        int v = (node < n) ? (g_deg[node] - 1) : 0;
        sScan[0][t] = v;
        __syncthreads();
        int p = 0;
        for (int off = 1; off < 256; off <<= 1) {
            sScan[p ^ 1][t] = sScan[p][t] + ((t >= off) ? sScan[p][t - off] : 0);
            p ^= 1;
            __syncthreads();
        }
        int incl = sScan[p][t];
        if (node < n) {
            int ex = g_blockOff[c] + incl - v;
            g_rowptr[node] = ex;
            g_cursor[node] = ex;
            if (node == n - 1) g_rowptr[n] = g_blockOff[c] + incl;
        }
        __syncthreads();
    }
    gridbar(nb);

    // P6: place edges (dst-sorted)
    for (int i = gtid; i < e; i += NT) {
        int s = src[i], d = dst[i];
        int pos = atomicAdd(&g_cursor[d], 1);
        float nv = __ldg(&g_dinv[s]) * __ldg(&g_dinv[d]);
        g_edge[pos] = make_int2(s, __float_as_int(nv));
    }
    gridbar(nb);

    // ---- layer 1 ----
    dev_gather<4>(x, g_B, n, gtid, NT);
    gridbar(nb);
    dev_gemm_stats<4, 16>(g_B, W1, b1, g_C, pS0, n, gtid, NT, sW, sAux, sAux + 64, sAux + 128);
    gridbar(nb);

    // ---- layer 2 ----
    dev_bn_elu<16>(g_C, pS0, g1, bt1, g_A, n, gtid, NT);
    gridbar(nb);
    dev_gather<16>(g_A, g_B, n, gtid, NT);
    gridbar(nb);
    dev_gemm_stats<16, 32>(g_B, W2, b2, g_C, pS1, n, gtid, NT, sW, sAux, sAux + 64, sAux + 128);
    gridbar(nb);

    // ---- layer 3 ----
    dev_bn_elu<32>(g_C, pS1, g2, bt2, g_A, n, gtid, NT);
    gridbar(nb);
    dev_gather<32>(g_A, g_B, n, gtid, NT);
    gridbar(nb);
    dev_gemm_stats<32, 64>(g_B, W3, b3, g_C, pS2, n, gtid, NT, sW, sAux, sAux + 64, sAux + 128);
    // k_mlp (second launch) consumes g_C + pS2
}

// ----------------- fused relu+BN+ELU + MLP + log_softmax -----------------
__global__ void __launch_bounds__(128)
k_mlp(const float* __restrict__ g, const float* __restrict__ bt,
      const float* __restrict__ Wf1, const float* __restrict__ bf1,
      const float* __restrict__ Wf2, const float* __restrict__ bf2,
      const float* __restrict__ Wf3, const float* __restrict__ bf3,
      float* __restrict__ out, int n) {
    const float* c = g_C;
    const float* stats_in = g_stats + 256;
    __shared__ float sW1[64 * 32], sb1[32];
    __shared__ float sW2[32 * 16], sb2[16];
    __shared__ float sW3[16 * 2], sb3[2];
    __shared__ float smean[64], sscale[64], sbt[64];
    for (int i = threadIdx.x; i < 64 * 32; i += blockDim.x) sW1[i] = Wf1[i];
    for (int i = threadIdx.x; i < 32 * 16; i += blockDim.x) sW2[i] = Wf2[i];
    for (int i = threadIdx.x; i < 32; i += blockDim.x) sW3[i] = Wf3[i];
    if (threadIdx.x < 32) sb1[threadIdx.x] = bf1[threadIdx.x];
    if (threadIdx.x < 16) sb2[threadIdx.x] = bf2[threadIdx.x];
    if (threadIdx.x < 2) sb3[threadIdx.x] = bf3[threadIdx.x];
    if (threadIdx.x < 64) {
        int col = threadIdx.x;
        float inv_n = 1.0f / (float)n;
        float mean = stats_in[col] * inv_n;
        float var = stats_in[64 + col] * inv_n - mean * mean;
        smean[col] = mean;
        sscale[col] = rsqrtf(var + EPS) * g[col];
        sbt[col] = bt[col];
    }
    __syncthreads();
    int node = blockIdx.x * blockDim.x + threadIdx.x;
    if (node >= n) return;

    float x[64];
    const float4* hp = reinterpret_cast<const float4*>(c + (size_t)node * 64);
#pragma unroll
    for (int k4 = 0; k4 < 16; k4++) {
        float4 v4 = hp[k4];
        float tmp[4] = {v4.x, v4.y, v4.z, v4.w};
#pragma unroll
        for (int j = 0; j < 4; j++) {
            int k = k4 * 4 + j;
            float v = fmaxf(tmp[j], 0.0f);
            float y = (v - smean[k]) * sscale[k] + sbt[k];
            x[k] = (y > 0.0f) ? y : expm1f(y);
        }
    }

    float t1[32];
#pragma unroll 4
    for (int j = 0; j < 32; j++) {
        float acc = sb1[j];
#pragma unroll
        for (int k = 0; k < 64; k++) acc = fmaf(x[k], sW1[k * 32 + j], acc);
        t1[j] = (acc > 0.0f) ? acc : expm1f(acc);
    }

    float t2[16];
#pragma unroll 4
    for (int j = 0; j < 16; j++) {
        float acc = sb2[j];
#pragma unroll
        for (int k = 0; k < 32; k++) acc = fmaf(t1[k], sW2[k * 16 + j], acc);
        t2[j] = (acc > 0.0f) ? acc : expm1f(acc);
    }

    float o0 = sb3[0], o1 = sb3[1];
#pragma unroll
    for (int k = 0; k < 16; k++) {
        o0 = fmaf(t2[k], sW3[k * 2 + 0], o0);
        o1 = fmaf(t2[k], sW3[k * 2 + 1], o1);
    }
    float m = fmaxf(o0, o1);
    float lse = m + logf(expf(o0 - m) + expf(o1 - m));
    out[node * 2 + 0] = o0 - lse;
    out[node * 2 + 1] = o1 - lse;
}

// ----------------- launch -----------------
extern "C" void kernel_launch(void* const* d_in, const int* in_sizes, int n_in,
                              void* d_out, int out_size) {
    const float* x   = (const float*)d_in[0];
    const int* eidx  = (const int*)d_in[1];
    const float* W1  = (const float*)d_in[2];
    const float* b1  = (const float*)d_in[3];
    const float* g1  = (const float*)d_in[4];
    const float* bt1 = (const float*)d_in[5];
    const float* W2  = (const float*)d_in[6];
    const float* b2  = (const float*)d_in[7];
    const float* g2  = (const float*)d_in[8];
    const float* bt2 = (const float*)d_in[9];
    const float* W3  = (const float*)d_in[10];
    const float* b3  = (const float*)d_in[11];
    const float* g3  = (const float*)d_in[12];
    const float* bt3 = (const float*)d_in[13];
    const float* Wf1 = (const float*)d_in[14];
    const float* bf1 = (const float*)d_in[15];
    const float* Wf2 = (const float*)d_in[16];
    const float* bf2 = (const float*)d_in[17];
    const float* Wf3 = (const float*)d_in[18];
    const float* bf3 = (const float*)d_in[19];
    float* out = (float*)d_out;

    const int n = in_sizes[0] / 4;
    const int e = in_sizes[1] / 2;
    const int* src = eidx;
    const int* dst = eidx + e;

    // All-resident grid size (host queries are allocation-free & capture-safe)
    int dev = 0;
    cudaGetDevice(&dev);
    int sms = 0;
    cudaDeviceGetAttribute(&sms, cudaDevAttrMultiProcessorCount, dev);
    int occ = 0;
    cudaOccupancyMaxActiveBlocksPerMultiprocessor(&occ, k_mega, 256, 0);
    int nb = sms * occ;
    if (nb < 1) nb = 1;
    if (nb > 2048) nb = 2048;

    k_mega<<<nb, 256>>>(x, src, dst, W1, b1, g1, bt1, W2, b2, g2, bt2, W3, b3, n, e, nb);
    k_mlp<<<(n + 127) / 128, 128>>>(g3, bt3, Wf1, bf1, Wf2, bf2, Wf3, bf3, out, n);
}

// round 8
// speedup vs baseline: 2.3266x; 2.3266x over previous
#include <cuda_runtime.h>
#include <math.h>

#define N_NODES 100000
#define E_EDGES 1200000
#define EPS 1e-5f

// -------- scratch (device globals; no allocation allowed) --------
__device__ float g_A[N_NODES * 64];     // act (post bn+elu)
__device__ float g_B[N_NODES * 64];     // agg (aggregated features, pre-GEMM)
__device__ float g_C[N_NODES * 64];     // conv output (pre-BN)
__device__ float g_dinv[N_NODES];
__device__ int   g_deg[N_NODES];        // 1 + in-degree
__device__ int   g_rowptr[N_NODES + 1];
__device__ int   g_cursor[N_NODES];
__device__ int2  g_edge[E_EDGES];       // {src, bits(norm)} sorted by dst
__device__ int   g_partial[512];
__device__ int   g_blockOff[512];
__device__ float g_stats[384];          // 3 slices of 128: [0..63] sum, [64..127] sumsq

// ----------------- degree -----------------
__global__ void k_deg_init(int* deg, int n) {
    int i = blockIdx.x * blockDim.x + threadIdx.x;
    if (i < n) deg[i] = 1;  // self loop
}

__global__ void k_deg_count(const int* __restrict__ dst, int* deg, int e) {
    int i = blockIdx.x * blockDim.x + threadIdx.x;
    if (i < e) atomicAdd(&deg[dst[i]], 1);
}

// dinv + per-block partial sums of edge-degree (fused)
__global__ void k_dinv_blocksums(const int* __restrict__ deg, float* dinv,
                                 int* partial, int n) {
    __shared__ int s[256];
    int i = blockIdx.x * 256 + threadIdx.x;
    int d = (i < n) ? deg[i] : 1;
    if (i < n) dinv[i] = rsqrtf((float)d);
    s[threadIdx.x] = (i < n) ? (d - 1) : 0;
    __syncthreads();
    for (int off = 128; off > 0; off >>= 1) {
        if (threadIdx.x < off) s[threadIdx.x] += s[threadIdx.x + off];
        __syncthreads();
    }
    if (threadIdx.x == 0) partial[blockIdx.x] = s[0];
}

__global__ void k_scan_partials(const int* __restrict__ partial, int* blockOff, int nb) {
    __shared__ int s[512];
    int t = threadIdx.x;
    int mine = (t < nb) ? partial[t] : 0;
    s[t] = mine;
    __syncthreads();
    for (int off = 1; off < 512; off <<= 1) {
        int v = (t >= off) ? s[t - off] : 0;
        __syncthreads();
        s[t] += v;
        __syncthreads();
    }
    if (t < nb) blockOff[t] = s[t] - mine;  // exclusive
}

__global__ void k_rowptr(const int* __restrict__ deg, const int* __restrict__ blockOff,
                         int* rowptr, int* cursor, int n) {
    __shared__ int s[256];
    int t = threadIdx.x;
    int i = blockIdx.x * 256 + t;
    int v = (i < n) ? (deg[i] - 1) : 0;
    s[t] = v;
    __syncthreads();
    for (int off = 1; off < 256; off <<= 1) {
        int u = (t >= off) ? s[t - off] : 0;
        __syncthreads();
        s[t] += u;
        __syncthreads();
    }
    if (i < n) {
        int ex = blockOff[blockIdx.x] + s[t] - v;
        rowptr[i] = ex;
        cursor[i] = ex;
        if (i == n - 1) rowptr[n] = blockOff[blockIdx.x] + s[t];
    }
}

__global__ void k_place(const int* __restrict__ src, const int* __restrict__ dst,
                        const float* __restrict__ dinv, int* cursor,
                        int2* edge_sorted, int e) {
    int i = blockIdx.x * blockDim.x + threadIdx.x;
    if (i >= e) return;
    int s = src[i], d = dst[i];
    int pos = atomicAdd(&cursor[d], 1);
    float nv = __ldg(&dinv[s]) * __ldg(&dinv[d]);
    edge_sorted[pos] = make_int2(s, __float_as_int(nv));
}

// ----------------- CSR gather on INPUT features (F = FIN) -----------------
template <int F>
__global__ void __launch_bounds__(256)
k_gather(const float* __restrict__ act, const int* __restrict__ rowptr,
         const int2* __restrict__ edges, const float* __restrict__ dinv,
         float* __restrict__ agg, float* __restrict__ stats_zero, int n) {
    constexpr int G = F / 4;
    if (blockIdx.x == 0 && threadIdx.x < 128) stats_zero[threadIdx.x] = 0.0f;
    int gid = blockIdx.x * blockDim.x + threadIdx.x;
    int node = gid / G;
    int q = gid & (G - 1);
    if (node >= n) return;

    const float4* a4 = reinterpret_cast<const float4*>(act);
    float di = dinv[node];
    float di2 = di * di;
    float4 hv = a4[(size_t)node * G + q];
    float4 a0, a1, a2, a3;
    a0.x = di2 * hv.x; a0.y = di2 * hv.y; a0.z = di2 * hv.z; a0.w = di2 * hv.w;
    a1 = make_float4(0.f, 0.f, 0.f, 0.f);
    a2 = make_float4(0.f, 0.f, 0.f, 0.f);
    a3 = make_float4(0.f, 0.f, 0.f, 0.f);

    int beg = rowptr[node], end = rowptr[node + 1];
    int i = beg;
    for (; i + 4 <= end; i += 4) {
        int2 e0 = __ldg(&edges[i + 0]);
        int2 e1 = __ldg(&edges[i + 1]);
        int2 e2 = __ldg(&edges[i + 2]);
        int2 e3 = __ldg(&edges[i + 3]);
        float4 s0 = a4[(size_t)e0.x * G + q];
        float4 s1 = a4[(size_t)e1.x * G + q];
        float4 s2 = a4[(size_t)e2.x * G + q];
        float4 s3 = a4[(size_t)e3.x * G + q];
        float n0 = __int_as_float(e0.y);
        float n1 = __int_as_float(e1.y);
        float n2 = __int_as_float(e2.y);
        float n3 = __int_as_float(e3.y);
        a0.x = fmaf(n0, s0.x, a0.x); a0.y = fmaf(n0, s0.y, a0.y);
        a0.z = fmaf(n0, s0.z, a0.z); a0.w = fmaf(n0, s0.w, a0.w);
        a1.x = fmaf(n1, s1.x, a1.x); a1.y = fmaf(n1, s1.y, a1.y);
        a1.z = fmaf(n1, s1.z, a1.z); a1.w = fmaf(n1, s1.w, a1.w);
        a2.x = fmaf(n2, s2.x, a2.x); a2.y = fmaf(n2, s2.y, a2.y);
        a2.z = fmaf(n2, s2.z, a2.z); a2.w = fmaf(n2, s2.w, a2.w);
        a3.x = fmaf(n3, s3.x, a3.x); a3.y = fmaf(n3, s3.y, a3.y);
        a3.z = fmaf(n3, s3.z, a3.z); a3.w = fmaf(n3, s3.w, a3.w);
    }
    for (; i < end; i++) {
        int2 e0 = __ldg(&edges[i]);
        float4 s0 = a4[(size_t)e0.x * G + q];
        float n0 = __int_as_float(e0.y);
        a1.x = fmaf(n0, s0.x, a1.x); a1.y = fmaf(n0, s0.y, a1.y);
        a1.z = fmaf(n0, s0.z, a1.z); a1.w = fmaf(n0, s0.w, a1.w);
    }
    float4 acc;
    acc.x = (a0.x + a1.x) + (a2.x + a3.x);
    acc.y = (a0.y + a1.y) + (a2.y + a3.y);
    acc.z = (a0.z + a1.z) + (a2.z + a3.z);
    acc.w = (a0.w + a1.w) + (a2.w + a3.w);
    reinterpret_cast<float4*>(agg)[(size_t)node * G + q] = acc;
}

// ----------------- GEMM (agg @ W + b) + fused relu-stats epilogue -----------------
template <int FIN, int FOUT>
__global__ void __launch_bounds__(256)
k_gemm_stats(const float* __restrict__ agg, const float* __restrict__ W,
             const float* __restrict__ b,
             float* __restrict__ outc, float* __restrict__ stats, int n) {
    __shared__ float sW[FIN * FOUT];
    __shared__ float sb[FOUT];
    __shared__ float sSum[FOUT], sSq[FOUT];
    for (int i = threadIdx.x; i < FIN * FOUT; i += blockDim.x) sW[i] = W[i];
    if (threadIdx.x < FOUT) {
        sb[threadIdx.x] = b[threadIdx.x];
        sSum[threadIdx.x] = 0.0f;
        sSq[threadIdx.x] = 0.0f;
    }
    __syncthreads();

    int node = blockIdx.x * blockDim.x + threadIdx.x;
    bool active = (node < n);
    int lane = threadIdx.x & 31;

    float xv[FIN];
#pragma unroll
    for (int k = 0; k < FIN; k++) xv[k] = active ? agg[(size_t)node * FIN + k] : 0.0f;

#pragma unroll 4
    for (int j = 0; j < FOUT; j++) {
        float acc = sb[j];
#pragma unroll
        for (int k = 0; k < FIN; k++) acc = fmaf(xv[k], sW[k * FOUT + j], acc);
        float r = active ? fmaxf(acc, 0.0f) : 0.0f;
        if (active) outc[(size_t)node * FOUT + j] = acc;
        float q = r * r;
#pragma unroll
        for (int off = 16; off > 0; off >>= 1) {
            r += __shfl_xor_sync(0xffffffffu, r, off);
            q += __shfl_xor_sync(0xffffffffu, q, off);
        }
        if (lane == 0) {
            atomicAdd(&sSum[j], r);
            atomicAdd(&sSq[j], q);
        }
    }
    __syncthreads();
    if (threadIdx.x < FOUT) {
        atomicAdd(&stats[threadIdx.x], sSum[threadIdx.x]);
        atomicAdd(&stats[64 + threadIdx.x], sSq[threadIdx.x]);
    }
}

// ----------------- relu + BN + ELU (elementwise) -----------------
template <int F>
__global__ void k_bn_elu(const float* __restrict__ c, const float* __restrict__ stats_in,
                         const float* __restrict__ g, const float* __restrict__ bt,
                         float* __restrict__ act, int n) {
    __shared__ float smean[F], sscale[F], sbt[F];
    if (threadIdx.x < F) {
        int col = threadIdx.x;
        float inv_n = 1.0f / (float)n;
        float mean = stats_in[col] * inv_n;
        float var = stats_in[64 + col] * inv_n - mean * mean;
        smean[col] = mean;
        sscale[col] = rsqrtf(var + EPS) * g[col];
        sbt[col] = bt[col];
    }
    __syncthreads();
    long idx = (long)blockIdx.x * blockDim.x + threadIdx.x;
    if (idx >= (long)n * F) return;
    int col = (int)(idx & (F - 1));
    float v = fmaxf(c[idx], 0.0f);
    float y = (v - smean[col]) * sscale[col] + sbt[col];
    act[idx] = (y > 0.0f) ? y : expm1f(y);
}

// ----------------- fused relu+BN+ELU + MLP + log_softmax -----------------
// Outer-product accumulation, ALL loops fully unrolled -> no dynamically-indexed
// local arrays, everything stays in registers (the round<=7 version spilled
// t1/t2/x to local memory via partial unrolls -> 358us of DRAM traffic).
__global__ void __launch_bounds__(128)
k_mlp(const float* __restrict__ c, const float* __restrict__ stats_in,
      const float* __restrict__ g, const float* __restrict__ bt,
      const float* __restrict__ Wf1, const float* __restrict__ bf1,
      const float* __restrict__ Wf2, const float* __restrict__ bf2,
      const float* __restrict__ Wf3, const float* __restrict__ bf3,
      float* __restrict__ out, int n) {
    __shared__ float sW1[64 * 32], sb1[32];
    __shared__ float sW2[32 * 16], sb2[16];
    __shared__ float sW3[16 * 2], sb3[2];
    __shared__ float smean[64], sscale[64], sbt[64];
    for (int i = threadIdx.x; i < 64 * 32; i += blockDim.x) sW1[i] = Wf1[i];
    for (int i = threadIdx.x; i < 32 * 16; i += blockDim.x) sW2[i] = Wf2[i];
    for (int i = threadIdx.x; i < 32; i += blockDim.x) sW3[i] = Wf3[i];
    if (threadIdx.x < 32) sb1[threadIdx.x] = bf1[threadIdx.x];
    if (threadIdx.x < 16) sb2[threadIdx.x] = bf2[threadIdx.x];
    if (threadIdx.x < 2) sb3[threadIdx.x] = bf3[threadIdx.x];
    if (threadIdx.x < 64) {
        int col = threadIdx.x;
        float inv_n = 1.0f / (float)n;
        float mean = stats_in[col] * inv_n;
        float var = stats_in[64 + col] * inv_n - mean * mean;
        smean[col] = mean;
        sscale[col] = rsqrtf(var + EPS) * g[col];
        sbt[col] = bt[col];
    }
    __syncthreads();
    int node = blockIdx.x * blockDim.x + threadIdx.x;
    if (node >= n) return;

    // t1 = elu(bn_elu(c) @ W1 + b1), accumulated outer-product style:
    // process 4 input features at a time; t1[32] fully unrolled -> registers.
    float t1[32];
#pragma unroll
    for (int j = 0; j < 32; j++) t1[j] = sb1[j];

    const float4* hp = reinterpret_cast<const float4*>(c + (size_t)node * 64);
#pragma unroll
    for (int k4 = 0; k4 < 16; k4++) {
        float4 v4 = hp[k4];
        float x0, x1, x2, x3;
        {
            float v = fmaxf(v4.x, 0.0f);
            float y = (v - smean[k4 * 4 + 0]) * sscale[k4 * 4 + 0] + sbt[k4 * 4 + 0];
            x0 = (y > 0.0f) ? y : expm1f(y);
        }
        {
            float v = fmaxf(v4.y, 0.0f);
            float y = (v - smean[k4 * 4 + 1]) * sscale[k4 * 4 + 1] + sbt[k4 * 4 + 1];
            x1 = (y > 0.0f) ? y : expm1f(y);
        }
        {
            float v = fmaxf(v4.z, 0.0f);
            float y = (v - smean[k4 * 4 + 2]) * sscale[k4 * 4 + 2] + sbt[k4 * 4 + 2];
            x2 = (y > 0.0f) ? y : expm1f(y);
        }
        {
            float v = fmaxf(v4.w, 0.0f);
            float y = (v - smean[k4 * 4 + 3]) * sscale[k4 * 4 + 3] + sbt[k4 * 4 + 3];
            x3 = (y > 0.0f) ? y : expm1f(y);
        }
#pragma unroll
        for (int j = 0; j < 32; j++) {
            float t = t1[j];
            t = fmaf(x0, sW1[(k4 * 4 + 0) * 32 + j], t);
            t = fmaf(x1, sW1[(k4 * 4 + 1) * 32 + j], t);
            t = fmaf(x2, sW1[(k4 * 4 + 2) * 32 + j], t);
            t = fmaf(x3, sW1[(k4 * 4 + 3) * 32 + j], t);
            t1[j] = t;
        }
    }
#pragma unroll
    for (int j = 0; j < 32; j++) t1[j] = (t1[j] > 0.0f) ? t1[j] : expm1f(t1[j]);

    float t2[16];
#pragma unroll
    for (int j = 0; j < 16; j++) t2[j] = sb2[j];
#pragma unroll
    for (int k = 0; k < 32; k++) {
#pragma unroll
        for (int j = 0; j < 16; j++) t2[j] = fmaf(t1[k], sW2[k * 16 + j], t2[j]);
    }
#pragma unroll
    for (int j = 0; j < 16; j++) t2[j] = (t2[j] > 0.0f) ? t2[j] : expm1f(t2[j]);

    float o0 = sb3[0], o1 = sb3[1];
#pragma unroll
    for (int k = 0; k < 16; k++) {
        o0 = fmaf(t2[k], sW3[k * 2 + 0], o0);
        o1 = fmaf(t2[k], sW3[k * 2 + 1], o1);
    }
    float m = fmaxf(o0, o1);
    float lse = m + logf(expf(o0 - m) + expf(o1 - m));
    out[node * 2 + 0] = o0 - lse;
    out[node * 2 + 1] = o1 - lse;
}

// ----------------- launch -----------------
extern "C" void kernel_launch(void* const* d_in, const int* in_sizes, int n_in,
                              void* d_out, int out_size) {
    const float* x   = (const float*)d_in[0];
    const int* eidx  = (const int*)d_in[1];
    const float* W1  = (const float*)d_in[2];
    const float* b1  = (const float*)d_in[3];
    const float* g1  = (const float*)d_in[4];
    const float* bt1 = (const float*)d_in[5];
    const float* W2  = (const float*)d_in[6];
    const float* b2  = (const float*)d_in[7];
    const float* g2  = (const float*)d_in[8];
    const float* bt2 = (const float*)d_in[9];
    const float* W3  = (const float*)d_in[10];
    const float* b3  = (const float*)d_in[11];
    const float* g3  = (const float*)d_in[12];
    const float* bt3 = (const float*)d_in[13];
    const float* Wf1 = (const float*)d_in[14];
    const float* bf1 = (const float*)d_in[15];
    const float* Wf2 = (const float*)d_in[16];
    const float* bf2 = (const float*)d_in[17];
    const float* Wf3 = (const float*)d_in[18];
    const float* bf3 = (const float*)d_in[19];
    float* out = (float*)d_out;

    const int n = in_sizes[0] / 4;
    const int e = in_sizes[1] / 2;
    const int* src = eidx;
    const int* dst = eidx + e;

    float *pA, *pB, *pC, *pDinv, *pStats;
    int *pDeg, *pRowptr, *pCursor, *pPartial, *pBlockOff;
    int2* pEdge;
    cudaGetSymbolAddress((void**)&pA, g_A);
    cudaGetSymbolAddress((void**)&pB, g_B);
    cudaGetSymbolAddress((void**)&pC, g_C);
    cudaGetSymbolAddress((void**)&pDinv, g_dinv);
    cudaGetSymbolAddress((void**)&pDeg, g_deg);
    cudaGetSymbolAddress((void**)&pRowptr, g_rowptr);
    cudaGetSymbolAddress((void**)&pCursor, g_cursor);
    cudaGetSymbolAddress((void**)&pEdge, g_edge);
    cudaGetSymbolAddress((void**)&pPartial, g_partial);
    cudaGetSymbolAddress((void**)&pBlockOff, g_blockOff);
    cudaGetSymbolAddress((void**)&pStats, g_stats);
    float* pS0 = pStats;
    float* pS1 = pStats + 128;
    float* pS2 = pStats + 256;

    const int TB = 256;
    const int gn = (n + TB - 1) / TB;   // 391 blocks
    const int ge = (e + TB - 1) / TB;

    // degree / dinv / CSR build
    k_deg_init<<<gn, TB>>>(pDeg, n);
    k_deg_count<<<ge, TB>>>(dst, pDeg, e);
    k_dinv_blocksums<<<gn, TB>>>(pDeg, pDinv, pPartial, n);
    k_scan_partials<<<1, 512>>>(pPartial, pBlockOff, gn);
    k_rowptr<<<gn, TB>>>(pDeg, pBlockOff, pRowptr, pCursor, n);
    k_place<<<ge, TB>>>(src, dst, pDinv, pCursor, pEdge, e);

    // ---- layer 1: gather x (4) -> gemm 4->16 ----
    {
        k_gather<4><<<(n * 1 + TB - 1) / TB, TB>>>(x, pRowptr, pEdge, pDinv, pB, pS0, n);
        k_gemm_stats<4, 16><<<gn, TB>>>(pB, W1, b1, pC, pS0, n);
    }
    // ---- layer 2: bn_elu (16) -> gather (16) -> gemm 16->32 ----
    {
        k_bn_elu<16><<<(n * 16 + TB - 1) / TB, TB>>>(pC, pS0, g1, bt1, pA, n);
        k_gather<16><<<(n * 4 + TB - 1) / TB, TB>>>(pA, pRowptr, pEdge, pDinv, pB, pS1, n);
        k_gemm_stats<16, 32><<<gn, TB>>>(pB, W2, b2, pC, pS1, n);
    }
    // ---- layer 3: bn_elu (32) -> gather (32) -> gemm 32->64 ----
    {
        k_bn_elu<32><<<(n * 32 + TB - 1) / TB, TB>>>(pC, pS1, g2, bt2, pA, n);
        k_gather<32><<<(n * 8 + TB - 1) / TB, TB>>>(pA, pRowptr, pEdge, pDinv, pB, pS2, n);
        k_gemm_stats<32, 64><<<gn, TB>>>(pB, W3, b3, pC, pS2, n);
    }

    // ---- bn_elu of layer3 + MLP head + log_softmax ----
    k_mlp<<<(n + 127) / 128, 128>>>(pC, pS2, g3, bt3, Wf1, bf1, Wf2, bf2, Wf3, bf3, out, n);
}

// round 9
// speedup vs baseline: 2.7756x; 1.1930x over previous
#include <cuda_runtime.h>
#include <math.h>

#define N_NODES 100000
#define E_EDGES 1200000
#define EPS 1e-5f

// -------- scratch (device globals; no allocation allowed) --------
__device__ float g_A[N_NODES * 64];     // act (post bn+elu)
__device__ float g_C[N_NODES * 64];     // conv output (pre-BN)
__device__ float g_dinv[N_NODES];
__device__ int   g_deg[N_NODES];        // edge in-degree (memset to 0 each run)
__device__ int   g_rowptr[N_NODES + 1];
__device__ int   g_cursor[N_NODES];
__device__ int2  g_edge[E_EDGES];       // {src, bits(norm)} sorted by dst
__device__ int   g_partial[512];
__device__ int   g_blockOff[512];
__device__ float g_stats[384];          // 3 slices of 128: [0..63] sum, [64..127] sumsq

// ----------------- degree -----------------
__global__ void k_deg_count(const int* __restrict__ dst, int* deg, int e) {
    int i = blockIdx.x * blockDim.x + threadIdx.x;
    if (i < e) atomicAdd(&deg[dst[i]], 1);
}

// dinv (self-loop +1) + per-block partial sums of edge-degree (fused)
__global__ void k_dinv_blocksums(const int* __restrict__ deg, float* dinv,
                                 int* partial, int n) {
    __shared__ int s[256];
    int i = blockIdx.x * 256 + threadIdx.x;
    int d = (i < n) ? deg[i] : 0;
    if (i < n) dinv[i] = rsqrtf((float)(d + 1));
    s[threadIdx.x] = (i < n) ? d : 0;
    __syncthreads();
    for (int off = 128; off > 0; off >>= 1) {
        if (threadIdx.x < off) s[threadIdx.x] += s[threadIdx.x + off];
        __syncthreads();
    }
    if (threadIdx.x == 0) partial[blockIdx.x] = s[0];
}

__global__ void k_scan_partials(const int* __restrict__ partial, int* blockOff, int nb) {
    __shared__ int s[512];
    int t = threadIdx.x;
    int mine = (t < nb) ? partial[t] : 0;
    s[t] = mine;
    __syncthreads();
    for (int off = 1; off < 512; off <<= 1) {
        int v = (t >= off) ? s[t - off] : 0;
        __syncthreads();
        s[t] += v;
        __syncthreads();
    }
    if (t < nb) blockOff[t] = s[t] - mine;  // exclusive
}

__global__ void k_rowptr(const int* __restrict__ deg, const int* __restrict__ blockOff,
                         int* rowptr, int* cursor, int n) {
    __shared__ int s[256];
    int t = threadIdx.x;
    int i = blockIdx.x * 256 + t;
    int v = (i < n) ? deg[i] : 0;
    s[t] = v;
    __syncthreads();
    for (int off = 1; off < 256; off <<= 1) {
        int u = (t >= off) ? s[t - off] : 0;
        __syncthreads();
        s[t] += u;
        __syncthreads();
    }
    if (i < n) {
        int ex = blockOff[blockIdx.x] + s[t] - v;
        rowptr[i] = ex;
        cursor[i] = ex;
        if (i == n - 1) rowptr[n] = blockOff[blockIdx.x] + s[t];
    }
}

__global__ void k_place(const int* __restrict__ src, const int* __restrict__ dst,
                        const float* __restrict__ dinv, int* cursor,
                        int2* edge_sorted, int e) {
    int i = blockIdx.x * blockDim.x + threadIdx.x;
    if (i >= e) return;
    int s = src[i], d = dst[i];
    int pos = atomicAdd(&cursor[d], 1);
    float nv = __ldg(&dinv[s]) * __ldg(&dinv[d]);
    edge_sorted[pos] = make_int2(s, __float_as_int(nv));
}

// ----------------- FUSED: CSR gather (input width) + warp GEMM + relu-stats -----------------
// Group of G = FIN/4 lanes per node. Each lane gathers its 16B slice of the
// aggregated row, then the group does the FIN->FOUT GEMM via register shuffles.
// out[node] = (dinv^2*act[node] + sum norm_e*act[src]) @ W + b ; stats = sum/sumsq(relu(out))
template <int FIN, int FOUT>
__global__ void __launch_bounds__(256)
k_layer(const float* __restrict__ act, const int* __restrict__ rowptr,
        const int2* __restrict__ edges, const float* __restrict__ dinv,
        const float* __restrict__ W, const float* __restrict__ b,
        float* __restrict__ outc, float* __restrict__ stats, int n) {
    constexpr int G = FIN / 4;      // lanes per node
    constexpr int OPL = FOUT / G;   // outputs per lane (16, 8, 8)
    __shared__ float sW[FIN * FOUT];
    __shared__ float sb[FOUT];
    __shared__ float sSum[FOUT], sSq[FOUT];
    for (int i = threadIdx.x; i < FIN * FOUT; i += 256) sW[i] = W[i];
    if (threadIdx.x < FOUT) {
        sb[threadIdx.x] = b[threadIdx.x];
        sSum[threadIdx.x] = 0.0f;
        sSq[threadIdx.x] = 0.0f;
    }
    __syncthreads();

    int gid = blockIdx.x * 256 + threadIdx.x;
    int node = gid / G;
    int q = gid & (G - 1);
    bool active = (node < n);
    int lane = threadIdx.x & 31;

    // ---- gather phase ----
    float4 a0 = make_float4(0.f, 0.f, 0.f, 0.f), a1 = a0, a2 = a0, a3 = a0;
    if (active) {
        const float4* a4 = reinterpret_cast<const float4*>(act);
        float di = dinv[node];
        float di2 = di * di;
        float4 hv = a4[(size_t)node * G + q];
        a0.x = di2 * hv.x; a0.y = di2 * hv.y; a0.z = di2 * hv.z; a0.w = di2 * hv.w;
        int beg = rowptr[node], end = rowptr[node + 1];
        int i = beg;
        for (; i + 4 <= end; i += 4) {
            int2 e0 = __ldg(&edges[i + 0]);
            int2 e1 = __ldg(&edges[i + 1]);
            int2 e2 = __ldg(&edges[i + 2]);
            int2 e3 = __ldg(&edges[i + 3]);
            float4 s0 = a4[(size_t)e0.x * G + q];
            float4 s1 = a4[(size_t)e1.x * G + q];
            float4 s2 = a4[(size_t)e2.x * G + q];
            float4 s3 = a4[(size_t)e3.x * G + q];
            float n0 = __int_as_float(e0.y), n1 = __int_as_float(e1.y);
            float n2 = __int_as_float(e2.y), n3 = __int_as_float(e3.y);
            a0.x = fmaf(n0, s0.x, a0.x); a0.y = fmaf(n0, s0.y, a0.y);
            a0.z = fmaf(n0, s0.z, a0.z); a0.w = fmaf(n0, s0.w, a0.w);
            a1.x = fmaf(n1, s1.x, a1.x); a1.y = fmaf(n1, s1.y, a1.y);
            a1.z = fmaf(n1, s1.z, a1.z); a1.w = fmaf(n1, s1.w, a1.w);
            a2.x = fmaf(n2, s2.x, a2.x); a2.y = fmaf(n2, s2.y, a2.y);
            a2.z = fmaf(n2, s2.z, a2.z); a2.w = fmaf(n2, s2.w, a2.w);
            a3.x = fmaf(n3, s3.x, a3.x); a3.y = fmaf(n3, s3.y, a3.y);
            a3.z = fmaf(n3, s3.z, a3.z); a3.w = fmaf(n3, s3.w, a3.w);
        }
        for (; i < end; i++) {
            int2 e0 = __ldg(&edges[i]);
            float4 s0 = a4[(size_t)e0.x * G + q];
            float n0 = __int_as_float(e0.y);
            a1.x = fmaf(n0, s0.x, a1.x); a1.y = fmaf(n0, s0.y, a1.y);
            a1.z = fmaf(n0, s0.z, a1.z); a1.w = fmaf(n0, s0.w, a1.w);
        }
    }
    float in0 = (a0.x + a1.x) + (a2.x + a3.x);
    float in1 = (a0.y + a1.y) + (a2.y + a3.y);
    float in2 = (a0.z + a1.z) + (a2.z + a3.z);
    float in3 = (a0.w + a1.w) + (a2.w + a3.w);
    __syncwarp();

    // ---- warp GEMM phase: broadcast 4 inputs per round within the G-lane group ----
    float o[OPL];
#pragma unroll
    for (int i = 0; i < OPL; i++) o[i] = sb[q * OPL + i];
    int base = lane & ~(G - 1);
#pragma unroll
    for (int r = 0; r < G; r++) {
        float x0 = __shfl_sync(0xffffffffu, in0, base + r);
        float x1 = __shfl_sync(0xffffffffu, in1, base + r);
        float x2 = __shfl_sync(0xffffffffu, in2, base + r);
        float x3 = __shfl_sync(0xffffffffu, in3, base + r);
        int k = r * 4;
#pragma unroll
        for (int i = 0; i < OPL; i++) {
            int col = q * OPL + i;
            float t = o[i];
            t = fmaf(x0, sW[(k + 0) * FOUT + col], t);
            t = fmaf(x1, sW[(k + 1) * FOUT + col], t);
            t = fmaf(x2, sW[(k + 2) * FOUT + col], t);
            t = fmaf(x3, sW[(k + 3) * FOUT + col], t);
            o[i] = t;
        }
    }
    if (active) {
#pragma unroll
        for (int i = 0; i < OPL; i += 4) {
            float4 v = make_float4(o[i], o[i + 1], o[i + 2], o[i + 3]);
            *reinterpret_cast<float4*>(outc + (size_t)node * FOUT + q * OPL + i) = v;
        }
    }

    // ---- relu-stats: reduce over lanes with the same q (offsets G..16) ----
#pragma unroll
    for (int i = 0; i < OPL; i++) {
        float r = active ? fmaxf(o[i], 0.0f) : 0.0f;
        float s2 = r * r;
#pragma unroll
        for (int off = G; off < 32; off <<= 1) {
            r += __shfl_xor_sync(0xffffffffu, r, off);
            s2 += __shfl_xor_sync(0xffffffffu, s2, off);
        }
        if (lane < G) {
            atomicAdd(&sSum[q * OPL + i], r);
            atomicAdd(&sSq[q * OPL + i], s2);
        }
    }
    __syncthreads();
    if (threadIdx.x < FOUT) {
        atomicAdd(&stats[threadIdx.x], sSum[threadIdx.x]);
        atomicAdd(&stats[64 + threadIdx.x], sSq[threadIdx.x]);
    }
}

// ----------------- relu + BN + ELU (elementwise) -----------------
template <int F>
__global__ void k_bn_elu(const float* __restrict__ c, const float* __restrict__ stats_in,
                         const float* __restrict__ g, const float* __restrict__ bt,
                         float* __restrict__ act, int n) {
    __shared__ float smean[F], sscale[F], sbt[F];
    if (threadIdx.x < F) {
        int col = threadIdx.x;
        float inv_n = 1.0f / (float)n;
        float mean = stats_in[col] * inv_n;
        float var = stats_in[64 + col] * inv_n - mean * mean;
        smean[col] = mean;
        sscale[col] = rsqrtf(var + EPS) * g[col];
        sbt[col] = bt[col];
    }
    __syncthreads();
    long idx = (long)blockIdx.x * blockDim.x + threadIdx.x;
    if (idx >= (long)n * F) return;
    int col = (int)(idx & (F - 1));
    float v = fmaxf(c[idx], 0.0f);
    float y = (v - smean[col]) * sscale[col] + sbt[col];
    act[idx] = (y > 0.0f) ? y : expm1f(y);
}

// ----------------- fused relu+BN+ELU + MLP + log_softmax (all regs, no spills) -----------------
__global__ void __launch_bounds__(128)
k_mlp(const float* __restrict__ c, const float* __restrict__ stats_in,
      const float* __restrict__ g, const float* __restrict__ bt,
      const float* __restrict__ Wf1, const float* __restrict__ bf1,
      const float* __restrict__ Wf2, const float* __restrict__ bf2,
      const float* __restrict__ Wf3, const float* __restrict__ bf3,
      float* __restrict__ out, int n) {
    __shared__ float sW1[64 * 32], sb1[32];
    __shared__ float sW2[32 * 16], sb2[16];
    __shared__ float sW3[16 * 2], sb3[2];
    __shared__ float smean[64], sscale[64], sbt[64];
    for (int i = threadIdx.x; i < 64 * 32; i += blockDim.x) sW1[i] = Wf1[i];
    for (int i = threadIdx.x; i < 32 * 16; i += blockDim.x) sW2[i] = Wf2[i];
    for (int i = threadIdx.x; i < 32; i += blockDim.x) sW3[i] = Wf3[i];
    if (threadIdx.x < 32) sb1[threadIdx.x] = bf1[threadIdx.x];
    if (threadIdx.x < 16) sb2[threadIdx.x] = bf2[threadIdx.x];
    if (threadIdx.x < 2) sb3[threadIdx.x] = bf3[threadIdx.x];
    if (threadIdx.x < 64) {
        int col = threadIdx.x;
        float inv_n = 1.0f / (float)n;
        float mean = stats_in[col] * inv_n;
        float var = stats_in[64 + col] * inv_n - mean * mean;
        smean[col] = mean;
        sscale[col] = rsqrtf(var + EPS) * g[col];
        sbt[col] = bt[col];
    }
    __syncthreads();
    int node = blockIdx.x * blockDim.x + threadIdx.x;
    if (node >= n) return;

    float t1[32];
#pragma unroll
    for (int j = 0; j < 32; j++) t1[j] = sb1[j];

    const float4* hp = reinterpret_cast<const float4*>(c + (size_t)node * 64);
#pragma unroll
    for (int k4 = 0; k4 < 16; k4++) {
        float4 v4 = hp[k4];
        float x0, x1, x2, x3;
        {
            float v = fmaxf(v4.x, 0.0f);
            float y = (v - smean[k4 * 4 + 0]) * sscale[k4 * 4 + 0] + sbt[k4 * 4 + 0];
            x0 = (y > 0.0f) ? y : expm1f(y);
        }
        {
            float v = fmaxf(v4.y, 0.0f);
            float y = (v - smean[k4 * 4 + 1]) * sscale[k4 * 4 + 1] + sbt[k4 * 4 + 1];
            x1 = (y > 0.0f) ? y : expm1f(y);
        }
        {
            float v = fmaxf(v4.z, 0.0f);
            float y = (v - smean[k4 * 4 + 2]) * sscale[k4 * 4 + 2] + sbt[k4 * 4 + 2];
            x2 = (y > 0.0f) ? y : expm1f(y);
        }
        {
            float v = fmaxf(v4.w, 0.0f);
            float y = (v - smean[k4 * 4 + 3]) * sscale[k4 * 4 + 3] + sbt[k4 * 4 + 3];
            x3 = (y > 0.0f) ? y : expm1f(y);
        }
#pragma unroll
        for (int j = 0; j < 32; j++) {
            float t = t1[j];
            t = fmaf(x0, sW1[(k4 * 4 + 0) * 32 + j], t);
            t = fmaf(x1, sW1[(k4 * 4 + 1) * 32 + j], t);
            t = fmaf(x2, sW1[(k4 * 4 + 2) * 32 + j], t);
            t = fmaf(x3, sW1[(k4 * 4 + 3) * 32 + j], t);
            t1[j] = t;
        }
    }
#pragma unroll
    for (int j = 0; j < 32; j++) t1[j] = (t1[j] > 0.0f) ? t1[j] : expm1f(t1[j]);

    float t2[16];
#pragma unroll
    for (int j = 0; j < 16; j++) t2[j] = sb2[j];
#pragma unroll
    for (int k = 0; k < 32; k++) {
#pragma unroll
        for (int j = 0; j < 16; j++) t2[j] = fmaf(t1[k], sW2[k * 16 + j], t2[j]);
    }
#pragma unroll
    for (int j = 0; j < 16; j++) t2[j] = (t2[j] > 0.0f) ? t2[j] : expm1f(t2[j]);

    float o0 = sb3[0], o1 = sb3[1];
#pragma unroll
    for (int k = 0; k < 16; k++) {
        o0 = fmaf(t2[k], sW3[k * 2 + 0], o0);
        o1 = fmaf(t2[k], sW3[k * 2 + 1], o1);
    }
    float m = fmaxf(o0, o1);
    float lse = m + logf(expf(o0 - m) + expf(o1 - m));
    out[node * 2 + 0] = o0 - lse;
    out[node * 2 + 1] = o1 - lse;
}

// ----------------- launch -----------------
extern "C" void kernel_launch(void* const* d_in, const int* in_sizes, int n_in,
                              void* d_out, int out_size) {
    const float* x   = (const float*)d_in[0];
    const int* eidx  = (const int*)d_in[1];
    const float* W1  = (const float*)d_in[2];
    const float* b1  = (const float*)d_in[3];
    const float* g1  = (const float*)d_in[4];
    const float* bt1 = (const float*)d_in[5];
    const float* W2  = (const float*)d_in[6];
    const float* b2  = (const float*)d_in[7];
    const float* g2  = (const float*)d_in[8];
    const float* bt2 = (const float*)d_in[9];
    const float* W3  = (const float*)d_in[10];
    const float* b3  = (const float*)d_in[11];
    const float* g3  = (const float*)d_in[12];
    const float* bt3 = (const float*)d_in[13];
    const float* Wf1 = (const float*)d_in[14];
    const float* bf1 = (const float*)d_in[15];
    const float* Wf2 = (const float*)d_in[16];
    const float* bf2 = (const float*)d_in[17];
    const float* Wf3 = (const float*)d_in[18];
    const float* bf3 = (const float*)d_in[19];
    float* out = (float*)d_out;

    const int n = in_sizes[0] / 4;
    const int e = in_sizes[1] / 2;
    const int* src = eidx;
    const int* dst = eidx + e;

    float *pA, *pC, *pDinv, *pStats;
    int *pDeg, *pRowptr, *pCursor, *pPartial, *pBlockOff;
    int2* pEdge;
    cudaGetSymbolAddress((void**)&pA, g_A);
    cudaGetSymbolAddress((void**)&pC, g_C);
    cudaGetSymbolAddress((void**)&pDinv, g_dinv);
    cudaGetSymbolAddress((void**)&pDeg, g_deg);
    cudaGetSymbolAddress((void**)&pRowptr, g_rowptr);
    cudaGetSymbolAddress((void**)&pCursor, g_cursor);
    cudaGetSymbolAddress((void**)&pEdge, g_edge);
    cudaGetSymbolAddress((void**)&pPartial, g_partial);
    cudaGetSymbolAddress((void**)&pBlockOff, g_blockOff);
    cudaGetSymbolAddress((void**)&pStats, g_stats);
    float* pS0 = pStats;
    float* pS1 = pStats + 128;
    float* pS2 = pStats + 256;

    const int TB = 256;
    const int gn = (n + TB - 1) / TB;   // 391 blocks
    const int ge = (e + TB - 1) / TB;

    // zero degree + stats (memset nodes, graph-capturable)
    cudaMemsetAsync(pDeg, 0, (size_t)n * sizeof(int), 0);
    cudaMemsetAsync(pStats, 0, 384 * sizeof(float), 0);

    // degree / dinv / CSR build
    k_deg_count<<<ge, TB>>>(dst, pDeg, e);
    k_dinv_blocksums<<<gn, TB>>>(pDeg, pDinv, pPartial, n);
    k_scan_partials<<<1, 512>>>(pPartial, pBlockOff, gn);
    k_rowptr<<<gn, TB>>>(pDeg, pBlockOff, pRowptr, pCursor, n);
    k_place<<<ge, TB>>>(src, dst, pDinv, pCursor, pEdge, e);

    // ---- layer 1: fused gather(4) + gemm 4->16 + stats ----
    k_layer<4, 16><<<(n * 1 + TB - 1) / TB, TB>>>(x, pRowptr, pEdge, pDinv, W1, b1, pC, pS0, n);
    // ---- layer 2: bn_elu(16) -> fused gather(16) + gemm 16->32 + stats ----
    k_bn_elu<16><<<(n * 16 + TB - 1) / TB, TB>>>(pC, pS0, g1, bt1, pA, n);
    k_layer<16, 32><<<(n * 4 + TB - 1) / TB, TB>>>(pA, pRowptr, pEdge, pDinv, W2, b2, pC, pS1, n);
    // ---- layer 3: bn_elu(32) -> fused gather(32) + gemm 32->64 + stats ----
    k_bn_elu<32><<<(n * 32 + TB - 1) / TB, TB>>>(pC, pS1, g2, bt2, pA, n);
    k_layer<32, 64><<<(n * 8 + TB - 1) / TB, TB>>>(pA, pRowptr, pEdge, pDinv, W3, b3, pC, pS2, n);

    // ---- bn_elu of layer3 + MLP head + log_softmax ----
    k_mlp<<<(n + 127) / 128, 128>>>(pC, pS2, g3, bt3, Wf1, bf1, Wf2, bf2, Wf3, bf3, out, n);
}

// round 10
// speedup vs baseline: 2.9568x; 1.0653x over previous
#include <cuda_runtime.h>
#include <math.h>

#define N_NODES 100000
#define E_EDGES 1200000
#define EPS 1e-5f

// fast ELU: expm1 via single-MUFU exp (rel err ~1e-7 vs 1e-3 budget)
__device__ __forceinline__ float fast_elu(float y) {
    return (y > 0.0f) ? y : (__expf(y) - 1.0f);
}

// -------- scratch (device globals; no allocation allowed) --------
__device__ float g_A[N_NODES * 64];     // act (post bn+elu)
__device__ float g_C[N_NODES * 64];     // conv output (pre-BN)
__device__ float g_dinv[N_NODES];
__device__ int   g_deg[N_NODES];        // edge in-degree (memset to 0 each run)
__device__ int   g_rowptr[N_NODES + 1];
__device__ int   g_cursor[N_NODES];
__device__ int2  g_edge[E_EDGES];       // {src, bits(norm)} sorted by dst
__device__ int   g_partial[512];
__device__ float g_stats[384];          // 3 slices of 128: [0..63] sum, [64..127] sumsq

// ----------------- degree -----------------
__global__ void k_deg_count(const int* __restrict__ dst, int* deg, int e) {
    int i = blockIdx.x * blockDim.x + threadIdx.x;
    if (i < e) atomicAdd(&deg[dst[i]], 1);
}

// dinv (self-loop +1) + per-block partial sums of edge-degree + zero stats (fused)
__global__ void k_dinv_blocksums(const int* __restrict__ deg, float* dinv,
                                 int* partial, float* stats_zero, int n) {
    __shared__ int s[256];
    int i = blockIdx.x * 256 + threadIdx.x;
    int d = (i < n) ? deg[i] : 0;
    if (i < n) dinv[i] = rsqrtf((float)(d + 1));
    if (blockIdx.x == 0) {
        stats_zero[threadIdx.x] = 0.0f;
        stats_zero[threadIdx.x + 128] = 0.0f;
    } else if (blockIdx.x == 1 && threadIdx.x < 128) {
        stats_zero[threadIdx.x + 256] = 0.0f;
    }
    s[threadIdx.x] = (i < n) ? d : 0;
    __syncthreads();
    for (int off = 128; off > 0; off >>= 1) {
        if (threadIdx.x < off) s[threadIdx.x] += s[threadIdx.x + off];
        __syncthreads();
    }
    if (threadIdx.x == 0) partial[blockIdx.x] = s[0];
}

// rowptr + cursor; each block redundantly scans ALL chunk partials in shared
// (391 ints -> trivially cheap) then does its local 256-node scan.
__global__ void k_rowptr(const int* __restrict__ deg, const int* __restrict__ partial,
                         int* rowptr, int* cursor, int n, int nchunks) {
    __shared__ int sp[2][512];
    __shared__ int s[2][256];
    int t = threadIdx.x;
    // inclusive scan of partials (512 slots, 2 per thread)
#pragma unroll
    for (int h = 0; h < 2; h++) {
        int idx = t + h * 256;
        sp[0][idx] = (idx < nchunks) ? partial[idx] : 0;
    }
    __syncthreads();
    int p = 0;
    for (int off = 1; off < 512; off <<= 1) {
#pragma unroll
        for (int h = 0; h < 2; h++) {
            int idx = t + h * 256;
            sp[p ^ 1][idx] = sp[p][idx] + ((idx >= off) ? sp[p][idx - off] : 0);
        }
        p ^= 1;
        __syncthreads();
    }
    int c = blockIdx.x;  // one chunk per block
    int blockOff = (c > 0) ? sp[p][c - 1] : 0;

    int i = c * 256 + t;
    int v = (i < n) ? deg[i] : 0;
    s[0][t] = v;
    __syncthreads();
    int q = 0;
    for (int off = 1; off < 256; off <<= 1) {
        s[q ^ 1][t] = s[q][t] + ((t >= off) ? s[q][t - off] : 0);
        q ^= 1;
        __syncthreads();
    }
    if (i < n) {
        int ex = blockOff + s[q][t] - v;
        rowptr[i] = ex;
        cursor[i] = ex;
        if (i == n - 1) rowptr[n] = blockOff + s[q][t];
    }
}

__global__ void k_place(const int* __restrict__ src, const int* __restrict__ dst,
                        const float* __restrict__ dinv, int* cursor,
                        int2* edge_sorted, int e) {
    int i = blockIdx.x * blockDim.x + threadIdx.x;
    if (i >= e) return;
    int s = src[i], d = dst[i];
    int pos = atomicAdd(&cursor[d], 1);
    float nv = __ldg(&dinv[s]) * __ldg(&dinv[d]);
    edge_sorted[pos] = make_int2(s, __float_as_int(nv));
}

// ----------------- FUSED: CSR gather (input width) + warp GEMM + relu-stats -----------------
template <int FIN, int FOUT>
__global__ void __launch_bounds__(256)
k_layer(const float* __restrict__ act, const int* __restrict__ rowptr,
        const int2* __restrict__ edges, const float* __restrict__ dinv,
        const float* __restrict__ W, const float* __restrict__ b,
        float* __restrict__ outc, float* __restrict__ stats, int n) {
    constexpr int G = FIN / 4;      // lanes per node
    constexpr int OPL = FOUT / G;   // outputs per lane (16, 8, 8)
    __shared__ float sW[FIN * FOUT];
    __shared__ float sb[FOUT];
    __shared__ float sSum[FOUT], sSq[FOUT];
    for (int i = threadIdx.x; i < FIN * FOUT; i += 256) sW[i] = W[i];
    if (threadIdx.x < FOUT) {
        sb[threadIdx.x] = b[threadIdx.x];
        sSum[threadIdx.x] = 0.0f;
        sSq[threadIdx.x] = 0.0f;
    }
    __syncthreads();

    int gid = blockIdx.x * 256 + threadIdx.x;
    int node = gid / G;
    int q = gid & (G - 1);
    bool active = (node < n);
    int lane = threadIdx.x & 31;

    // ---- gather phase ----
    float4 a0 = make_float4(0.f, 0.f, 0.f, 0.f), a1 = a0, a2 = a0, a3 = a0;
    if (active) {
        const float4* a4 = reinterpret_cast<const float4*>(act);
        float di = dinv[node];
        float di2 = di * di;
        float4 hv = a4[(size_t)node * G + q];
        a0.x = di2 * hv.x; a0.y = di2 * hv.y; a0.z = di2 * hv.z; a0.w = di2 * hv.w;
        int beg = rowptr[node], end = rowptr[node + 1];
        int i = beg;
        for (; i + 4 <= end; i += 4) {
            int2 e0 = __ldg(&edges[i + 0]);
            int2 e1 = __ldg(&edges[i + 1]);
            int2 e2 = __ldg(&edges[i + 2]);
            int2 e3 = __ldg(&edges[i + 3]);
            float4 s0 = a4[(size_t)e0.x * G + q];
            float4 s1 = a4[(size_t)e1.x * G + q];
            float4 s2 = a4[(size_t)e2.x * G + q];
            float4 s3 = a4[(size_t)e3.x * G + q];
            float n0 = __int_as_float(e0.y), n1 = __int_as_float(e1.y);
            float n2 = __int_as_float(e2.y), n3 = __int_as_float(e3.y);
            a0.x = fmaf(n0, s0.x, a0.x); a0.y = fmaf(n0, s0.y, a0.y);
            a0.z = fmaf(n0, s0.z, a0.z); a0.w = fmaf(n0, s0.w, a0.w);
            a1.x = fmaf(n1, s1.x, a1.x); a1.y = fmaf(n1, s1.y, a1.y);
            a1.z = fmaf(n1, s1.z, a1.z); a1.w = fmaf(n1, s1.w, a1.w);
            a2.x = fmaf(n2, s2.x, a2.x); a2.y = fmaf(n2, s2.y, a2.y);
            a2.z = fmaf(n2, s2.z, a2.z); a2.w = fmaf(n2, s2.w, a2.w);
            a3.x = fmaf(n3, s3.x, a3.x); a3.y = fmaf(n3, s3.y, a3.y);
            a3.z = fmaf(n3, s3.z, a3.z); a3.w = fmaf(n3, s3.w, a3.w);
        }
        for (; i < end; i++) {
            int2 e0 = __ldg(&edges[i]);
            float4 s0 = a4[(size_t)e0.x * G + q];
            float n0 = __int_as_float(e0.y);
            a1.x = fmaf(n0, s0.x, a1.x); a1.y = fmaf(n0, s0.y, a1.y);
            a1.z = fmaf(n0, s0.z, a1.z); a1.w = fmaf(n0, s0.w, a1.w);
        }
    }
    float in0 = (a0.x + a1.x) + (a2.x + a3.x);
    float in1 = (a0.y + a1.y) + (a2.y + a3.y);
    float in2 = (a0.z + a1.z) + (a2.z + a3.z);
    float in3 = (a0.w + a1.w) + (a2.w + a3.w);
    __syncwarp();

    // ---- warp GEMM phase ----
    float o[OPL];
#pragma unroll
    for (int i = 0; i < OPL; i++) o[i] = sb[q * OPL + i];
    int base = lane & ~(G - 1);
#pragma unroll
    for (int r = 0; r < G; r++) {
        float x0 = __shfl_sync(0xffffffffu, in0, base + r);
        float x1 = __shfl_sync(0xffffffffu, in1, base + r);
        float x2 = __shfl_sync(0xffffffffu, in2, base + r);
        float x3 = __shfl_sync(0xffffffffu, in3, base + r);
        int k = r * 4;
#pragma unroll
        for (int i = 0; i < OPL; i++) {
            int col = q * OPL + i;
            float t = o[i];
            t = fmaf(x0, sW[(k + 0) * FOUT + col], t);
            t = fmaf(x1, sW[(k + 1) * FOUT + col], t);
            t = fmaf(x2, sW[(k + 2) * FOUT + col], t);
            t = fmaf(x3, sW[(k + 3) * FOUT + col], t);
            o[i] = t;
        }
    }
    if (active) {
#pragma unroll
        for (int i = 0; i < OPL; i += 4) {
            float4 v = make_float4(o[i], o[i + 1], o[i + 2], o[i + 3]);
            *reinterpret_cast<float4*>(outc + (size_t)node * FOUT + q * OPL + i) = v;
        }
    }

    // ---- relu-stats ----
#pragma unroll
    for (int i = 0; i < OPL; i++) {
        float r = active ? fmaxf(o[i], 0.0f) : 0.0f;
        float s2 = r * r;
#pragma unroll
        for (int off = G; off < 32; off <<= 1) {
            r += __shfl_xor_sync(0xffffffffu, r, off);
            s2 += __shfl_xor_sync(0xffffffffu, s2, off);
        }
        if (lane < G) {
            atomicAdd(&sSum[q * OPL + i], r);
            atomicAdd(&sSq[q * OPL + i], s2);
        }
    }
    __syncthreads();
    if (threadIdx.x < FOUT) {
        atomicAdd(&stats[threadIdx.x], sSum[threadIdx.x]);
        atomicAdd(&stats[64 + threadIdx.x], sSq[threadIdx.x]);
    }
}

// ----------------- relu + BN + ELU (elementwise) -----------------
template <int F>
__global__ void k_bn_elu(const float* __restrict__ c, const float* __restrict__ stats_in,
                         const float* __restrict__ g, const float* __restrict__ bt,
                         float* __restrict__ act, int n) {
    __shared__ float smean[F], sscale[F], sbt[F];
    if (threadIdx.x < F) {
        int col = threadIdx.x;
        float inv_n = 1.0f / (float)n;
        float mean = stats_in[col] * inv_n;
        float var = stats_in[64 + col] * inv_n - mean * mean;
        smean[col] = mean;
        sscale[col] = rsqrtf(var + EPS) * g[col];
        sbt[col] = bt[col];
    }
    __syncthreads();
    long idx = (long)blockIdx.x * blockDim.x + threadIdx.x;
    if (idx >= (long)n * F) return;
    int col = (int)(idx & (F - 1));
    float v = fmaxf(c[idx], 0.0f);
    float y = (v - smean[col]) * sscale[col] + sbt[col];
    act[idx] = fast_elu(y);
}

// ----------------- fused relu+BN+ELU + MLP + log_softmax (all regs, no spills) -----------------
__global__ void __launch_bounds__(128)
k_mlp(const float* __restrict__ c, const float* __restrict__ stats_in,
      const float* __restrict__ g, const float* __restrict__ bt,
      const float* __restrict__ Wf1, const float* __restrict__ bf1,
      const float* __restrict__ Wf2, const float* __restrict__ bf2,
      const float* __restrict__ Wf3, const float* __restrict__ bf3,
      float* __restrict__ out, int n) {
    __shared__ float sW1[64 * 32], sb1[32];
    __shared__ float sW2[32 * 16], sb2[16];
    __shared__ float sW3[16 * 2], sb3[2];
    __shared__ float smean[64], sscale[64], sbt[64];
    for (int i = threadIdx.x; i < 64 * 32; i += blockDim.x) sW1[i] = Wf1[i];
    for (int i = threadIdx.x; i < 32 * 16; i += blockDim.x) sW2[i] = Wf2[i];
    for (int i = threadIdx.x; i < 32; i += blockDim.x) sW3[i] = Wf3[i];
    if (threadIdx.x < 32) sb1[threadIdx.x] = bf1[threadIdx.x];
    if (threadIdx.x < 16) sb2[threadIdx.x] = bf2[threadIdx.x];
    if (threadIdx.x < 2) sb3[threadIdx.x] = bf3[threadIdx.x];
    if (threadIdx.x < 64) {
        int col = threadIdx.x;
        float inv_n = 1.0f / (float)n;
        float mean = stats_in[col] * inv_n;
        float var = stats_in[64 + col] * inv_n - mean * mean;
        smean[col] = mean;
        sscale[col] = rsqrtf(var + EPS) * g[col];
        sbt[col] = bt[col];
    }
    __syncthreads();
    int node = blockIdx.x * blockDim.x + threadIdx.x;
    if (node >= n) return;

    float t1[32];
#pragma unroll
    for (int j = 0; j < 32; j++) t1[j] = sb1[j];

    const float4* hp = reinterpret_cast<const float4*>(c + (size_t)node * 64);
#pragma unroll
    for (int k4 = 0; k4 < 16; k4++) {
        float4 v4 = hp[k4];
        float x0 = fast_elu((fmaxf(v4.x, 0.0f) - smean[k4 * 4 + 0]) * sscale[k4 * 4 + 0] + sbt[k4 * 4 + 0]);
        float x1 = fast_elu((fmaxf(v4.y, 0.0f) - smean[k4 * 4 + 1]) * sscale[k4 * 4 + 1] + sbt[k4 * 4 + 1]);
        float x2 = fast_elu((fmaxf(v4.z, 0.0f) - smean[k4 * 4 + 2]) * sscale[k4 * 4 + 2] + sbt[k4 * 4 + 2]);
        float x3 = fast_elu((fmaxf(v4.w, 0.0f) - smean[k4 * 4 + 3]) * sscale[k4 * 4 + 3] + sbt[k4 * 4 + 3]);
#pragma unroll
        for (int j = 0; j < 32; j++) {
            float t = t1[j];
            t = fmaf(x0, sW1[(k4 * 4 + 0) * 32 + j], t);
            t = fmaf(x1, sW1[(k4 * 4 + 1) * 32 + j], t);
            t = fmaf(x2, sW1[(k4 * 4 + 2) * 32 + j], t);
            t = fmaf(x3, sW1[(k4 * 4 + 3) * 32 + j], t);
            t1[j] = t;
        }
    }
#pragma unroll
    for (int j = 0; j < 32; j++) t1[j] = fast_elu(t1[j]);

    float t2[16];
#pragma unroll
    for (int j = 0; j < 16; j++) t2[j] = sb2[j];
#pragma unroll
    for (int k = 0; k < 32; k++) {
#pragma unroll
        for (int j = 0; j < 16; j++) t2[j] = fmaf(t1[k], sW2[k * 16 + j], t2[j]);
    }
#pragma unroll
    for (int j = 0; j < 16; j++) t2[j] = fast_elu(t2[j]);

    float o0 = sb3[0], o1 = sb3[1];
#pragma unroll
    for (int k = 0; k < 16; k++) {
        o0 = fmaf(t2[k], sW3[k * 2 + 0], o0);
        o1 = fmaf(t2[k], sW3[k * 2 + 1], o1);
    }
    // log-softmax over 2 classes (fast math: log1p via __logf, |err| ~1e-7)
    float m = fmaxf(o0, o1);
    float lse = m + __logf(__expf(o0 - m) + __expf(o1 - m));
    out[node * 2 + 0] = o0 - lse;
    out[node * 2 + 1] = o1 - lse;
}

// ----------------- launch -----------------
extern "C" void kernel_launch(void* const* d_in, const int* in_sizes, int n_in,
                              void* d_out, int out_size) {
    const float* x   = (const float*)d_in[0];
    const int* eidx  = (const int*)d_in[1];
    const float* W1  = (const float*)d_in[2];
    const float* b1  = (const float*)d_in[3];
    const float* g1  = (const float*)d_in[4];
    const float* bt1 = (const float*)d_in[5];
    const float* W2  = (const float*)d_in[6];
    const float* b2  = (const float*)d_in[7];
    const float* g2  = (const float*)d_in[8];
    const float* bt2 = (const float*)d_in[9];
    const float* W3  = (const float*)d_in[10];
    const float* b3  = (const float*)d_in[11];
    const float* g3  = (const float*)d_in[12];
    const float* bt3 = (const float*)d_in[13];
    const float* Wf1 = (const float*)d_in[14];
    const float* bf1 = (const float*)d_in[15];
    const float* Wf2 = (const float*)d_in[16];
    const float* bf2 = (const float*)d_in[17];
    const float* Wf3 = (const float*)d_in[18];
    const float* bf3 = (const float*)d_in[19];
    float* out = (float*)d_out;

    const int n = in_sizes[0] / 4;
    const int e = in_sizes[1] / 2;
    const int* src = eidx;
    const int* dst = eidx + e;

    float *pA, *pC, *pDinv, *pStats;
    int *pDeg, *pRowptr, *pCursor, *pPartial;
    int2* pEdge;
    cudaGetSymbolAddress((void**)&pA, g_A);
    cudaGetSymbolAddress((void**)&pC, g_C);
    cudaGetSymbolAddress((void**)&pDinv, g_dinv);
    cudaGetSymbolAddress((void**)&pDeg, g_deg);
    cudaGetSymbolAddress((void**)&pRowptr, g_rowptr);
    cudaGetSymbolAddress((void**)&pCursor, g_cursor);
    cudaGetSymbolAddress((void**)&pEdge, g_edge);
    cudaGetSymbolAddress((void**)&pPartial, g_partial);
    cudaGetSymbolAddress((void**)&pStats, g_stats);
    float* pS0 = pStats;
    float* pS1 = pStats + 128;
    float* pS2 = pStats + 256;

    const int TB = 256;
    const int gn = (n + TB - 1) / TB;   // 391 blocks = chunks
    const int ge = (e + TB - 1) / TB;

    // zero degree (memset counts as the 1st graph node)
    cudaMemsetAsync(pDeg, 0, (size_t)n * sizeof(int), 0);

    // degree / dinv(+zero stats) / rowptr(fused scan) / place
    k_deg_count<<<ge, TB>>>(dst, pDeg, e);
    k_dinv_blocksums<<<gn, TB>>>(pDeg, pDinv, pPartial, pStats, n);
    k_rowptr<<<gn, TB>>>(pDeg, pPartial, pRowptr, pCursor, n, gn);
    k_place<<<ge, TB>>>(src, dst, pDinv, pCursor, pEdge, e);

    // ---- layer 1: fused gather(4) + gemm 4->16 + stats  [6th launch -> ncu -s 5 samples this] ----
    k_layer<4, 16><<<(n * 1 + TB - 1) / TB, TB>>>(x, pRowptr, pEdge, pDinv, W1, b1, pC, pS0, n);
    // ---- layer 2 ----
    k_bn_elu<16><<<(n * 16 + TB - 1) / TB, TB>>>(pC, pS0, g1, bt1, pA, n);
    k_layer<16, 32><<<(n * 4 + TB - 1) / TB, TB>>>(pA, pRowptr, pEdge, pDinv, W2, b2, pC, pS1, n);
    // ---- layer 3 ----
    k_bn_elu<32><<<(n * 32 + TB - 1) / TB, TB>>>(pC, pS1, g2, bt2, pA, n);
    k_layer<32, 64><<<(n * 8 + TB - 1) / TB, TB>>>(pA, pRowptr, pEdge, pDinv, W3, b3, pC, pS2, n);

    // ---- bn_elu of layer3 + MLP head + log_softmax ----
    k_mlp<<<(n + 127) / 128, 128>>>(pC, pS2, g3, bt3, Wf1, bf1, Wf2, bf2, Wf3, bf3, out, n);
}

// round 11
// speedup vs baseline: 3.0158x; 1.0200x over previous
#include <cuda_runtime.h>
#include <math.h>

#define N_NODES 100000
#define E_EDGES 1200000
#define EPS 1e-5f

// fast ELU: expm1 via single-MUFU exp (rel err ~1e-7 vs 1e-3 budget)
__device__ __forceinline__ float fast_elu(float y) {
    return (y > 0.0f) ? y : (__expf(y) - 1.0f);
}

// -------- scratch (device globals; no allocation allowed) --------
__device__ float g_A[N_NODES * 64];     // act (post bn+elu)
__device__ float g_C[N_NODES * 64];     // conv output (pre-BN)
__device__ float g_dinv[N_NODES];
__device__ int   g_deg[N_NODES];        // edge in-degree (memset to 0 each run)
__device__ int   g_rowptr[N_NODES + 1];
__device__ int   g_cursor[N_NODES];
__device__ int2  g_edge[E_EDGES];       // {src, bits(norm)} sorted by dst
__device__ int   g_partial[512];
__device__ float g_stats[384];          // 3 slices of 128: [0..63] sum, [64..127] sumsq

// ----------------- degree -----------------
__global__ void k_deg_count(const int* __restrict__ dst, int* deg, int e) {
    int i = blockIdx.x * blockDim.x + threadIdx.x;
    if (i < e) atomicAdd(&deg[dst[i]], 1);
}

// dinv (self-loop +1) + per-block partial sums of edge-degree + zero stats (fused)
__global__ void k_dinv_blocksums(const int* __restrict__ deg, float* dinv,
                                 int* partial, float* stats_zero, int n) {
    __shared__ int s[256];
    int i = blockIdx.x * 256 + threadIdx.x;
    int d = (i < n) ? deg[i] : 0;
    if (i < n) dinv[i] = rsqrtf((float)(d + 1));
    if (blockIdx.x == 0) {
        stats_zero[threadIdx.x] = 0.0f;
        stats_zero[threadIdx.x + 128] = 0.0f;
    } else if (blockIdx.x == 1 && threadIdx.x < 128) {
        stats_zero[threadIdx.x + 256] = 0.0f;
    }
    s[threadIdx.x] = (i < n) ? d : 0;
    __syncthreads();
    for (int off = 128; off > 0; off >>= 1) {
        if (threadIdx.x < off) s[threadIdx.x] += s[threadIdx.x + off];
        __syncthreads();
    }
    if (threadIdx.x == 0) partial[blockIdx.x] = s[0];
}

// rowptr + cursor; each block redundantly scans ALL chunk partials in shared.
__global__ void k_rowptr(const int* __restrict__ deg, const int* __restrict__ partial,
                         int* rowptr, int* cursor, int n, int nchunks) {
    __shared__ int sp[2][512];
    __shared__ int s[2][256];
    int t = threadIdx.x;
#pragma unroll
    for (int h = 0; h < 2; h++) {
        int idx = t + h * 256;
        sp[0][idx] = (idx < nchunks) ? partial[idx] : 0;
    }
    __syncthreads();
    int p = 0;
    for (int off = 1; off < 512; off <<= 1) {
#pragma unroll
        for (int h = 0; h < 2; h++) {
            int idx = t + h * 256;
            sp[p ^ 1][idx] = sp[p][idx] + ((idx >= off) ? sp[p][idx - off] : 0);
        }
        p ^= 1;
        __syncthreads();
    }
    int c = blockIdx.x;
    int blockOff = (c > 0) ? sp[p][c - 1] : 0;

    int i = c * 256 + t;
    int v = (i < n) ? deg[i] : 0;
    s[0][t] = v;
    __syncthreads();
    int q = 0;
    for (int off = 1; off < 256; off <<= 1) {
        s[q ^ 1][t] = s[q][t] + ((t >= off) ? s[q][t - off] : 0);
        q ^= 1;
        __syncthreads();
    }
    if (i < n) {
        int ex = blockOff + s[q][t] - v;
        rowptr[i] = ex;
        cursor[i] = ex;
        if (i == n - 1) rowptr[n] = blockOff + s[q][t];
    }
}

__global__ void k_place(const int* __restrict__ src, const int* __restrict__ dst,
                        const float* __restrict__ dinv, int* cursor,
                        int2* edge_sorted, int e) {
    int i = blockIdx.x * blockDim.x + threadIdx.x;
    if (i >= e) return;
    int s = src[i], d = dst[i];
    int pos = atomicAdd(&cursor[d], 1);
    float nv = __ldg(&dinv[s]) * __ldg(&dinv[d]);
    edge_sorted[pos] = make_int2(s, __float_as_int(nv));
}

// ----------------- FUSED layer: edge-striped CSR gather + warp GEMM + relu-stats -----------------
// GS = G*S lanes per node (G = FIN/4 feature quads, S edge stripes).
// Lane (s,q): accumulates quad q over edges {beg+s, beg+s+S, ...}; stripes folded
// via shfl_xor; then the GS-lane group does FIN->FOUT GEMM, OPL=FOUT/GS outputs/lane.
template <int FIN, int FOUT, int S>
__global__ void __launch_bounds__(256)
k_layer(const float* __restrict__ act, const int* __restrict__ rowptr,
        const int2* __restrict__ edges, const float* __restrict__ dinv,
        const float* __restrict__ W, const float* __restrict__ b,
        float* __restrict__ outc, float* __restrict__ stats, int n) {
    constexpr int G = FIN / 4;
    constexpr int GS = G * S;           // lanes per node (8, 16, 32)
    constexpr int OPL = FOUT / GS;      // outputs per lane (2)
    __shared__ float sW[FIN * FOUT];
    __shared__ float sb[FOUT];
    __shared__ float sSum[FOUT], sSq[FOUT];
    for (int i = threadIdx.x; i < FIN * FOUT; i += 256) sW[i] = W[i];
    if (threadIdx.x < FOUT) {
        sb[threadIdx.x] = b[threadIdx.x];
        sSum[threadIdx.x] = 0.0f;
        sSq[threadIdx.x] = 0.0f;
    }
    __syncthreads();

    int gid = blockIdx.x * 256 + threadIdx.x;
    int node = gid / GS;
    int idx = gid & (GS - 1);           // lane within node group
    int s = idx / G;                    // edge stripe
    int q = idx & (G - 1);              // feature quad
    bool active = (node < n);
    int lane = threadIdx.x & 31;

    // ---- gather phase (stripe s of this node's edges) ----
    float4 a0 = make_float4(0.f, 0.f, 0.f, 0.f), a1 = a0;
    if (active) {
        const float4* a4 = reinterpret_cast<const float4*>(act);
        if (s == 0) {
            float di = dinv[node];
            float di2 = di * di;
            float4 hv = a4[(size_t)node * G + q];
            a0.x = di2 * hv.x; a0.y = di2 * hv.y; a0.z = di2 * hv.z; a0.w = di2 * hv.w;
        }
        int beg = rowptr[node], end = rowptr[node + 1];
        int i = beg + s;
        for (; i + S < end; i += 2 * S) {
            int2 e0 = __ldg(&edges[i]);
            int2 e1 = __ldg(&edges[i + S]);
            float4 s0 = a4[(size_t)e0.x * G + q];
            float4 s1 = a4[(size_t)e1.x * G + q];
            float n0 = __int_as_float(e0.y), n1 = __int_as_float(e1.y);
            a0.x = fmaf(n0, s0.x, a0.x); a0.y = fmaf(n0, s0.y, a0.y);
            a0.z = fmaf(n0, s0.z, a0.z); a0.w = fmaf(n0, s0.w, a0.w);
            a1.x = fmaf(n1, s1.x, a1.x); a1.y = fmaf(n1, s1.y, a1.y);
            a1.z = fmaf(n1, s1.z, a1.z); a1.w = fmaf(n1, s1.w, a1.w);
        }
        if (i < end) {
            int2 e0 = __ldg(&edges[i]);
            float4 s0 = a4[(size_t)e0.x * G + q];
            float n0 = __int_as_float(e0.y);
            a0.x = fmaf(n0, s0.x, a0.x); a0.y = fmaf(n0, s0.y, a0.y);
            a0.z = fmaf(n0, s0.z, a0.z); a0.w = fmaf(n0, s0.w, a0.w);
        }
    }
    float in0 = a0.x + a1.x;
    float in1 = a0.y + a1.y;
    float in2 = a0.z + a1.z;
    float in3 = a0.w + a1.w;
    __syncwarp();

    // fold edge stripes: stripe bits live at offsets G..GS/2
#pragma unroll
    for (int off = G; off < GS; off <<= 1) {
        in0 += __shfl_xor_sync(0xffffffffu, in0, off);
        in1 += __shfl_xor_sync(0xffffffffu, in1, off);
        in2 += __shfl_xor_sync(0xffffffffu, in2, off);
        in3 += __shfl_xor_sync(0xffffffffu, in3, off);
    }

    // ---- warp GEMM phase: GS lanes per node, OPL outputs per lane ----
    float o[OPL];
#pragma unroll
    for (int i = 0; i < OPL; i++) o[i] = sb[idx * OPL + i];
    int base = lane & ~(GS - 1);
#pragma unroll
    for (int r = 0; r < G; r++) {
        float x0 = __shfl_sync(0xffffffffu, in0, base + r);
        float x1 = __shfl_sync(0xffffffffu, in1, base + r);
        float x2 = __shfl_sync(0xffffffffu, in2, base + r);
        float x3 = __shfl_sync(0xffffffffu, in3, base + r);
        int k = r * 4;
#pragma unroll
        for (int i = 0; i < OPL; i++) {
            int col = idx * OPL + i;
            float t = o[i];
            t = fmaf(x0, sW[(k + 0) * FOUT + col], t);
            t = fmaf(x1, sW[(k + 1) * FOUT + col], t);
            t = fmaf(x2, sW[(k + 2) * FOUT + col], t);
            t = fmaf(x3, sW[(k + 3) * FOUT + col], t);
            o[i] = t;
        }
    }
    if (active) {
        float2 v = make_float2(o[0], o[1]);
        *reinterpret_cast<float2*>(outc + (size_t)node * FOUT + idx * OPL) = v;
    }

    // ---- relu-stats: fold across node groups within the warp (offsets GS..16) ----
#pragma unroll
    for (int i = 0; i < OPL; i++) {
        float r = active ? fmaxf(o[i], 0.0f) : 0.0f;
        float s2 = r * r;
#pragma unroll
        for (int off = GS; off < 32; off <<= 1) {
            r += __shfl_xor_sync(0xffffffffu, r, off);
            s2 += __shfl_xor_sync(0xffffffffu, s2, off);
        }
        if (lane < GS) {
            atomicAdd(&sSum[idx * OPL + i], r);
            atomicAdd(&sSq[idx * OPL + i], s2);
        }
    }
    __syncthreads();
    if (threadIdx.x < FOUT) {
        atomicAdd(&stats[threadIdx.x], sSum[threadIdx.x]);
        atomicAdd(&stats[64 + threadIdx.x], sSq[threadIdx.x]);
    }
}

// ----------------- relu + BN + ELU (elementwise) -----------------
template <int F>
__global__ void k_bn_elu(const float* __restrict__ c, const float* __restrict__ stats_in,
                         const float* __restrict__ g, const float* __restrict__ bt,
                         float* __restrict__ act, int n) {
    __shared__ float smean[F], sscale[F], sbt[F];
    if (threadIdx.x < F) {
        int col = threadIdx.x;
        float inv_n = 1.0f / (float)n;
        float mean = stats_in[col] * inv_n;
        float var = stats_in[64 + col] * inv_n - mean * mean;
        smean[col] = mean;
        sscale[col] = rsqrtf(var + EPS) * g[col];
        sbt[col] = bt[col];
    }
    __syncthreads();
    long idx = (long)blockIdx.x * blockDim.x + threadIdx.x;
    if (idx >= (long)n * F) return;
    int col = (int)(idx & (F - 1));
    float v = fmaxf(c[idx], 0.0f);
    float y = (v - smean[col]) * sscale[col] + sbt[col];
    act[idx] = fast_elu(y);
}

// ----------------- fused relu+BN+ELU + MLP + log_softmax (all regs, no spills) -----------------
__global__ void __launch_bounds__(128)
k_mlp(const float* __restrict__ c, const float* __restrict__ stats_in,
      const float* __restrict__ g, const float* __restrict__ bt,
      const float* __restrict__ Wf1, const float* __restrict__ bf1,
      const float* __restrict__ Wf2, const float* __restrict__ bf2,
      const float* __restrict__ Wf3, const float* __restrict__ bf3,
      float* __restrict__ out, int n) {
    __shared__ float sW1[64 * 32], sb1[32];
    __shared__ float sW2[32 * 16], sb2[16];
    __shared__ float sW3[16 * 2], sb3[2];
    __shared__ float smean[64], sscale[64], sbt[64];
    for (int i = threadIdx.x; i < 64 * 32; i += blockDim.x) sW1[i] = Wf1[i];
    for (int i = threadIdx.x; i < 32 * 16; i += blockDim.x) sW2[i] = Wf2[i];
    for (int i = threadIdx.x; i < 32; i += blockDim.x) sW3[i] = Wf3[i];
    if (threadIdx.x < 32) sb1[threadIdx.x] = bf1[threadIdx.x];
    if (threadIdx.x < 16) sb2[threadIdx.x] = bf2[threadIdx.x];
    if (threadIdx.x < 2) sb3[threadIdx.x] = bf3[threadIdx.x];
    if (threadIdx.x < 64) {
        int col = threadIdx.x;
        float inv_n = 1.0f / (float)n;
        float mean = stats_in[col] * inv_n;
        float var = stats_in[64 + col] * inv_n - mean * mean;
        smean[col] = mean;
        sscale[col] = rsqrtf(var + EPS) * g[col];
        sbt[col] = bt[col];
    }
    __syncthreads();
    int node = blockIdx.x * blockDim.x + threadIdx.x;
    if (node >= n) return;

    float t1[32];
#pragma unroll
    for (int j = 0; j < 32; j++) t1[j] = sb1[j];

    const float4* hp = reinterpret_cast<const float4*>(c + (size_t)node * 64);
#pragma unroll
    for (int k4 = 0; k4 < 16; k4++) {
        float4 v4 = hp[k4];
        float x0 = fast_elu((fmaxf(v4.x, 0.0f) - smean[k4 * 4 + 0]) * sscale[k4 * 4 + 0] + sbt[k4 * 4 + 0]);
        float x1 = fast_elu((fmaxf(v4.y, 0.0f) - smean[k4 * 4 + 1]) * sscale[k4 * 4 + 1] + sbt[k4 * 4 + 1]);
        float x2 = fast_elu((fmaxf(v4.z, 0.0f) - smean[k4 * 4 + 2]) * sscale[k4 * 4 + 2] + sbt[k4 * 4 + 2]);
        float x3 = fast_elu((fmaxf(v4.w, 0.0f) - smean[k4 * 4 + 3]) * sscale[k4 * 4 + 3] + sbt[k4 * 4 + 3]);
#pragma unroll
        for (int j = 0; j < 32; j++) {
            float t = t1[j];
            t = fmaf(x0, sW1[(k4 * 4 + 0) * 32 + j], t);
            t = fmaf(x1, sW1[(k4 * 4 + 1) * 32 + j], t);
            t = fmaf(x2, sW1[(k4 * 4 + 2) * 32 + j], t);
            t = fmaf(x3, sW1[(k4 * 4 + 3) * 32 + j], t);
            t1[j] = t;
        }
    }
#pragma unroll
    for (int j = 0; j < 32; j++) t1[j] = fast_elu(t1[j]);

    float t2[16];
#pragma unroll
    for (int j = 0; j < 16; j++) t2[j] = sb2[j];
#pragma unroll
    for (int k = 0; k < 32; k++) {
#pragma unroll
        for (int j = 0; j < 16; j++) t2[j] = fmaf(t1[k], sW2[k * 16 + j], t2[j]);
    }
#pragma unroll
    for (int j = 0; j < 16; j++) t2[j] = fast_elu(t2[j]);

    float o0 = sb3[0], o1 = sb3[1];
#pragma unroll
    for (int k = 0; k < 16; k++) {
        o0 = fmaf(t2[k], sW3[k * 2 + 0], o0);
        o1 = fmaf(t2[k], sW3[k * 2 + 1], o1);
    }
    float m = fmaxf(o0, o1);
    float lse = m + __logf(__expf(o0 - m) + __expf(o1 - m));
    out[node * 2 + 0] = o0 - lse;
    out[node * 2 + 1] = o1 - lse;
}

// ----------------- launch -----------------
extern "C" void kernel_launch(void* const* d_in, const int* in_sizes, int n_in,
                              void* d_out, int out_size) {
    const float* x   = (const float*)d_in[0];
    const int* eidx  = (const int*)d_in[1];
    const float* W1  = (const float*)d_in[2];
    const float* b1  = (const float*)d_in[3];
    const float* g1  = (const float*)d_in[4];
    const float* bt1 = (const float*)d_in[5];
    const float* W2  = (const float*)d_in[6];
    const float* b2  = (const float*)d_in[7];
    const float* g2  = (const float*)d_in[8];
    const float* bt2 = (const float*)d_in[9];
    const float* W3  = (const float*)d_in[10];
    const float* b3  = (const float*)d_in[11];
    const float* g3  = (const float*)d_in[12];
    const float* bt3 = (const float*)d_in[13];
    const float* Wf1 = (const float*)d_in[14];
    const float* bf1 = (const float*)d_in[15];
    const float* Wf2 = (const float*)d_in[16];
    const float* bf2 = (const float*)d_in[17];
    const float* Wf3 = (const float*)d_in[18];
    const float* bf3 = (const float*)d_in[19];
    float* out = (float*)d_out;

    const int n = in_sizes[0] / 4;
    const int e = in_sizes[1] / 2;
    const int* src = eidx;
    const int* dst = eidx + e;

    float *pA, *pC, *pDinv, *pStats;
    int *pDeg, *pRowptr, *pCursor, *pPartial;
    int2* pEdge;
    cudaGetSymbolAddress((void**)&pA, g_A);
    cudaGetSymbolAddress((void**)&pC, g_C);
    cudaGetSymbolAddress((void**)&pDinv, g_dinv);
    cudaGetSymbolAddress((void**)&pDeg, g_deg);
    cudaGetSymbolAddress((void**)&pRowptr, g_rowptr);
    cudaGetSymbolAddress((void**)&pCursor, g_cursor);
    cudaGetSymbolAddress((void**)&pEdge, g_edge);
    cudaGetSymbolAddress((void**)&pPartial, g_partial);
    cudaGetSymbolAddress((void**)&pStats, g_stats);
    float* pS0 = pStats;
    float* pS1 = pStats + 128;
    float* pS2 = pStats + 256;

    const int TB = 256;
    const int gn = (n + TB - 1) / TB;   // 391 chunks
    const int ge = (e + TB - 1) / TB;

    cudaMemsetAsync(pDeg, 0, (size_t)n * sizeof(int), 0);

    // degree / dinv(+zero stats) / rowptr(fused scan) / place
    k_deg_count<<<ge, TB>>>(dst, pDeg, e);
    k_dinv_blocksums<<<gn, TB>>>(pDeg, pDinv, pPartial, pStats, n);
    k_rowptr<<<gn, TB>>>(pDeg, pPartial, pRowptr, pCursor, n, gn);
    k_place<<<ge, TB>>>(src, dst, pDinv, pCursor, pEdge, e);

    // ---- layer 1: 4->16, 8 lanes/node (S=8) ----
    k_layer<4, 16, 8><<<(n * 8 + TB - 1) / TB, TB>>>(x, pRowptr, pEdge, pDinv, W1, b1, pC, pS0, n);
    // ---- layer 2: 16->32, 16 lanes/node (S=4) ----
    k_bn_elu<16><<<(n * 16 + TB - 1) / TB, TB>>>(pC, pS0, g1, bt1, pA, n);
    k_layer<16, 32, 4><<<(n * 16 + TB - 1) / TB, TB>>>(pA, pRowptr, pEdge, pDinv, W2, b2, pC, pS1, n);
    // ---- layer 3: 32->64, 32 lanes/node (S=4) ----
    k_bn_elu<32><<<(n * 32 + TB - 1) / TB, TB>>>(pC, pS1, g2, bt2, pA, n);
    k_layer<32, 64, 4><<<(n * 32 + TB - 1) / TB, TB>>>(pA, pRowptr, pEdge, pDinv, W3, b3, pC, pS2, n);

    // ---- bn_elu of layer3 + MLP head + log_softmax ----
    k_mlp<<<(n + 127) / 128, 128>>>(pC, pS2, g3, bt3, Wf1, bf1, Wf2, bf2, Wf3, bf3, out, n);
}